// round 1
// baseline (speedup 1.0000x reference)
#include <cuda_runtime.h>
#include <math.h>

// Problem constants
// B=2048 windows, N=49 tokens, C=384, H=12 heads, hd=32, nW=64 masks
// qkv scratch laid out [B][H][N][hd]; attention out laid out [B][N][C]

__device__ float g_q[2048u*12*49*32];
__device__ float g_k[2048u*12*49*32];
__device__ float g_v[2048u*12*49*32];
__device__ float g_o[2048u*49*384];
__device__ float g_bt[169*12];
__device__ float g_rpb[12*49*49];

// ---------------------------------------------------------------------------
// CPB MLP: bias_table[t][h] = 16*sigmoid( sum_j relu(table[t]@w1[j]+b1[j]) * w2[h][j] )
// ---------------------------------------------------------------------------
__global__ void cpb_kernel(const float* __restrict__ table, const float* __restrict__ w1,
                           const float* __restrict__ b1, const float* __restrict__ w2) {
    __shared__ float red[16];
    int t = blockIdx.x;      // 0..168
    int j = threadIdx.x;     // 0..511
    float t0 = table[t * 2 + 0], t1 = table[t * 2 + 1];
    float h = fmaxf(fmaf(t0, w1[j * 2 + 0], fmaf(t1, w1[j * 2 + 1], b1[j])), 0.f);
    for (int hh = 0; hh < 12; hh++) {
        float v = h * w2[hh * 512 + j];
        #pragma unroll
        for (int o = 16; o > 0; o >>= 1) v += __shfl_down_sync(0xffffffffu, v, o);
        if ((j & 31) == 0) red[j >> 5] = v;
        __syncthreads();
        if (j == 0) {
            float s = 0.f;
            #pragma unroll
            for (int w = 0; w < 16; w++) s += red[w];
            g_bt[t * 12 + hh] = 16.f / (1.f + expf(-s));
        }
        __syncthreads();
    }
}

// rpb[h][i][j] = bias_table[idx[i][j]][h]
__global__ void gather_kernel(const int* __restrict__ idx) {
    int e = blockIdx.x * 256 + threadIdx.x;
    if (e >= 12 * 49 * 49) return;
    int h = e / 2401, ij = e - h * 2401;
    g_rpb[e] = g_bt[idx[ij] * 12 + h];
}

// ---------------------------------------------------------------------------
// SGEMM: C[M,Ncols] = A[M,384] @ B[Ncols,384]^T (+bias), 128x128x8 tiles.
// mode 0: QKV — epilogue scatters into g_q/g_k/g_v with concat bias
// mode 1: Proj — A := g_o, epilogue writes outp row-major + proj bias
// ---------------------------------------------------------------------------
__global__ void __launch_bounds__(256) gemm_kernel(
    const float* __restrict__ Ain, const float* __restrict__ Bw,
    int mode, const float* __restrict__ bq, const float* __restrict__ bv,
    const float* __restrict__ bp, float* __restrict__ outp)
{
    __shared__ float As[8][128];
    __shared__ float Bs[8][128];
    const float* A = (mode == 1) ? g_o : Ain;
    int bm = blockIdx.x, bn = blockIdx.y;
    int tid = threadIdx.x;
    int tx = tid & 15, ty = tid >> 4;
    int lrow = tid >> 1;
    int lcol = (tid & 1) * 4;
    const float* Ap = A  + (size_t)(bm * 128 + lrow) * 384 + lcol;
    const float* Bp = Bw + (size_t)(bn * 128 + lrow) * 384 + lcol;

    float acc[8][8];
    #pragma unroll
    for (int i = 0; i < 8; i++)
        #pragma unroll
        for (int j = 0; j < 8; j++) acc[i][j] = 0.f;

    float4 av = *(const float4*)(Ap);
    float4 bvv = *(const float4*)(Bp);

    for (int k0 = 0; k0 < 384; k0 += 8) {
        __syncthreads();
        As[lcol + 0][lrow] = av.x; As[lcol + 1][lrow] = av.y;
        As[lcol + 2][lrow] = av.z; As[lcol + 3][lrow] = av.w;
        Bs[lcol + 0][lrow] = bvv.x; Bs[lcol + 1][lrow] = bvv.y;
        Bs[lcol + 2][lrow] = bvv.z; Bs[lcol + 3][lrow] = bvv.w;
        __syncthreads();
        if (k0 + 8 < 384) {
            av = *(const float4*)(Ap + k0 + 8);
            bvv = *(const float4*)(Bp + k0 + 8);
        }
        #pragma unroll
        for (int kk = 0; kk < 8; kk++) {
            float a[8], b[8];
            *(float4*)&a[0] = *(const float4*)&As[kk][ty * 8];
            *(float4*)&a[4] = *(const float4*)&As[kk][ty * 8 + 4];
            *(float4*)&b[0] = *(const float4*)&Bs[kk][tx * 8];
            *(float4*)&b[4] = *(const float4*)&Bs[kk][tx * 8 + 4];
            #pragma unroll
            for (int i = 0; i < 8; i++)
                #pragma unroll
                for (int j = 0; j < 8; j++)
                    acc[i][j] = fmaf(a[i], b[j], acc[i][j]);
        }
    }

    if (mode == 0) {
        #pragma unroll
        for (int i = 0; i < 8; i++) {
            int m = bm * 128 + ty * 8 + i;
            int b = m / 49, nn = m - b * 49;
            #pragma unroll
            for (int j = 0; j < 8; j++) {
                int ncol = bn * 128 + tx * 8 + j;
                int which = ncol / 384;
                int rem = ncol - which * 384;
                int h = rem >> 5, d = rem & 31;
                float bias = (which == 0) ? bq[rem] : ((which == 2) ? bv[rem] : 0.f);
                float* dst = (which == 0) ? g_q : ((which == 1) ? g_k : g_v);
                dst[(((size_t)b * 12 + h) * 49 + nn) * 32 + d] = acc[i][j] + bias;
            }
        }
    } else {
        #pragma unroll
        for (int i = 0; i < 8; i++) {
            int m = bm * 128 + ty * 8 + i;
            #pragma unroll
            for (int j = 0; j < 8; j++) {
                int ncol = bn * 128 + tx * 8 + j;
                outp[(size_t)m * 384 + ncol] = acc[i][j] + bp[ncol];
            }
        }
    }
}

// ---------------------------------------------------------------------------
// Attention: one block per (window b, head h).
// ---------------------------------------------------------------------------
__global__ void __launch_bounds__(256) attn_kernel(const float* __restrict__ mask,
                                                   const float* __restrict__ logit_scale)
{
    __shared__ float sq[49 * 32];
    __shared__ float sk[49 * 32];
    __shared__ float sv[49 * 32];
    __shared__ float sS[49 * 49];
    int bh = blockIdx.x;
    int b = bh / 12, h = bh - b * 12;
    int tid = threadIdx.x;

    size_t base = (size_t)bh * 49 * 32;
    for (int u = tid; u < 392; u += 256) {
        ((float4*)sq)[u] = ((const float4*)(g_q + base))[u];
        ((float4*)sk)[u] = ((const float4*)(g_k + base))[u];
        ((float4*)sv)[u] = ((const float4*)(g_v + base))[u];
    }
    __syncthreads();

    // normalize q rows (and fold in logit scale) / k rows
    if (tid < 49) {
        float ss = 0.f;
        #pragma unroll
        for (int d = 0; d < 32; d++) { float x = sq[tid * 32 + d]; ss = fmaf(x, x, ss); }
        float sc = expf(fminf(logit_scale[h], 4.60517018598809136804f));  // log(100)
        float inv = sc / fmaxf(sqrtf(ss), 1e-12f);
        #pragma unroll
        for (int d = 0; d < 32; d++) sq[tid * 32 + d] *= inv;
    } else if (tid >= 64 && tid < 113) {
        int r = tid - 64;
        float ss = 0.f;
        #pragma unroll
        for (int d = 0; d < 32; d++) { float x = sk[r * 32 + d]; ss = fmaf(x, x, ss); }
        float inv = 1.f / fmaxf(sqrtf(ss), 1e-12f);
        #pragma unroll
        for (int d = 0; d < 32; d++) sk[r * 32 + d] *= inv;
    }
    __syncthreads();

    // S = qn @ kn^T   (5 threads per row, <=10 cols each)
    if (tid < 245) {
        int i = tid / 5, s5 = tid - i * 5;
        float4 qr[8];
        #pragma unroll
        for (int u = 0; u < 8; u++) qr[u] = ((const float4*)(sq + i * 32))[u];
        int j0 = s5 * 10;
        int j1 = j0 + 10 > 49 ? 49 : j0 + 10;
        for (int j = j0; j < j1; j++) {
            const float4* kr = (const float4*)(sk + j * 32);
            float accv = 0.f;
            #pragma unroll
            for (int u = 0; u < 8; u++) {
                float4 kv = kr[u];
                accv = fmaf(qr[u].x, kv.x, accv);
                accv = fmaf(qr[u].y, kv.y, accv);
                accv = fmaf(qr[u].z, kv.z, accv);
                accv = fmaf(qr[u].w, kv.w, accv);
            }
            sS[i * 49 + j] = accv;
        }
    }
    __syncthreads();

    // softmax over rows with rpb + mask added
    if (tid < 49) {
        int i = tid;
        const float* rp = g_rpb + (h * 49 + i) * 49;
        const float* mp = mask + ((size_t)(b & 63) * 49 + i) * 49;
        float mx = -1e30f;
        for (int j = 0; j < 49; j++) {
            float s = sS[i * 49 + j] + rp[j] + mp[j];
            sS[i * 49 + j] = s;
            mx = fmaxf(mx, s);
        }
        float sum = 0.f;
        for (int j = 0; j < 49; j++) {
            float e = expf(sS[i * 49 + j] - mx);
            sS[i * 49 + j] = e;
            sum += e;
        }
        float inv = 1.f / sum;
        for (int j = 0; j < 49; j++) sS[i * 49 + j] *= inv;
    }
    __syncthreads();

    // out = P @ V, write to [B][N][C] layout for proj GEMM
    for (int e = tid; e < 49 * 32; e += 256) {
        int i = e >> 5, d = e & 31;
        float accv = 0.f;
        for (int j = 0; j < 49; j++)
            accv = fmaf(sS[i * 49 + j], sv[j * 32 + d], accv);
        g_o[((size_t)b * 49 + i) * 384 + h * 32 + d] = accv;
    }
}

// ---------------------------------------------------------------------------
extern "C" void kernel_launch(void* const* d_in, const int* in_sizes, int n_in,
                              void* d_out, int out_size) {
    const float* x           = (const float*)d_in[0];
    const float* mask        = (const float*)d_in[1];
    const float* qkv_w       = (const float*)d_in[2];
    const float* q_bias      = (const float*)d_in[3];
    const float* v_bias      = (const float*)d_in[4];
    const float* logit_scale = (const float*)d_in[5];
    const float* cpb_w1      = (const float*)d_in[6];
    const float* cpb_b1      = (const float*)d_in[7];
    const float* cpb_w2      = (const float*)d_in[8];
    const float* proj_w      = (const float*)d_in[9];
    const float* proj_b      = (const float*)d_in[10];
    const float* table       = (const float*)d_in[11];
    const int*   idx         = (const int*)d_in[12];
    float* out = (float*)d_out;

    cpb_kernel<<<169, 512>>>(table, cpb_w1, cpb_b1, cpb_w2);
    gather_kernel<<<(12 * 2401 + 255) / 256, 256>>>(idx);
    gemm_kernel<<<dim3(784, 9), 256>>>(x, qkv_w, 0, q_bias, v_bias, nullptr, nullptr);
    attn_kernel<<<2048 * 12, 256>>>(mask, logit_scale);
    gemm_kernel<<<dim3(784, 3), 256>>>(nullptr, proj_w, 1, nullptr, nullptr, proj_b, out);
}

// round 4
// speedup vs baseline: 1.3113x; 1.3113x over previous
#include <cuda_runtime.h>
#include <math.h>
#include <stdint.h>

// B=2048 windows, N=49, C=384, H=12, hd=32, nW=64
__device__ float g_q  [2048u*12*49*32];
__device__ float g_k  [2048u*12*49*32];
__device__ float g_v  [2048u*12*49*32];
__device__ float g_ohi[2048u*49*384];   // attn out hi (tf32), [B][N][C]
__device__ float g_olo[2048u*49*384];   // attn out lo
__device__ float g_xhi[2048u*49*384];
__device__ float g_xlo[2048u*49*384];
__device__ float g_whi[1152*384];
__device__ float g_wlo[1152*384];
__device__ float g_phi[384*384];
__device__ float g_plo[384*384];
__device__ float g_bt [169*12];
__device__ float g_rpb[12*49*49];

// ---------------------------------------------------------------------------
__device__ __forceinline__ uint32_t smem_u32(const void* p) {
    uint32_t a;
    asm("{ .reg .u64 t; cvta.to.shared.u64 t, %1; cvt.u32.u64 %0, t; }" : "=r"(a) : "l"(p));
    return a;
}
__device__ __forceinline__ float tf32r(float x) {
    float y; asm("cvt.rna.tf32.f32 %0, %1;" : "=f"(y) : "f"(x)); return y;
}
__device__ __forceinline__ void cp_async16(uint32_t dst, const void* src) {
    asm volatile("cp.async.cg.shared.global [%0], [%1], 16;" :: "r"(dst), "l"(src));
}
#define CP_COMMIT() asm volatile("cp.async.commit_group;" ::: "memory")
template<int N> __device__ __forceinline__ void cp_wait() {
    asm volatile("cp.async.wait_group %0;" :: "n"(N) : "memory");
}
__device__ __forceinline__ void mma_tf32(float& c0, float& c1, float& c2, float& c3,
                                         uint32_t a0, uint32_t a1, uint32_t a2, uint32_t a3,
                                         uint32_t b0, uint32_t b1) {
    asm volatile("mma.sync.aligned.m16n8k8.row.col.f32.tf32.tf32.f32 "
                 "{%0,%1,%2,%3}, {%4,%5,%6,%7}, {%8,%9}, {%0,%1,%2,%3};"
                 : "+f"(c0), "+f"(c1), "+f"(c2), "+f"(c3)
                 : "r"(a0), "r"(a1), "r"(a2), "r"(a3), "r"(b0), "r"(b1));
}

// ---------------------------------------------------------------------------
// tf32 hi/lo split prepass: hi = tf32(x), lo = tf32(x - hi)
// ---------------------------------------------------------------------------
__global__ void split_kernel(const float* __restrict__ in, float* __restrict__ hi,
                             float* __restrict__ lo, int n4) {
    int i = blockIdx.x * 256 + threadIdx.x;
    if (i >= n4) return;
    float4 v = ((const float4*)in)[i];
    float4 h, l;
    h.x = tf32r(v.x); l.x = tf32r(v.x - h.x);
    h.y = tf32r(v.y); l.y = tf32r(v.y - h.y);
    h.z = tf32r(v.z); l.z = tf32r(v.z - h.z);
    h.w = tf32r(v.w); l.w = tf32r(v.w - h.w);
    ((float4*)hi)[i] = h;
    ((float4*)lo)[i] = l;
}

// ---------------------------------------------------------------------------
// CPB MLP + gather
// ---------------------------------------------------------------------------
__global__ void cpb_kernel(const float* __restrict__ table, const float* __restrict__ w1,
                           const float* __restrict__ b1, const float* __restrict__ w2) {
    __shared__ float red[16];
    int t = blockIdx.x, j = threadIdx.x;
    float t0 = table[t * 2 + 0], t1 = table[t * 2 + 1];
    float h = fmaxf(fmaf(t0, w1[j * 2 + 0], fmaf(t1, w1[j * 2 + 1], b1[j])), 0.f);
    for (int hh = 0; hh < 12; hh++) {
        float v = h * w2[hh * 512 + j];
        #pragma unroll
        for (int o = 16; o > 0; o >>= 1) v += __shfl_down_sync(0xffffffffu, v, o);
        if ((j & 31) == 0) red[j >> 5] = v;
        __syncthreads();
        if (j == 0) {
            float s = 0.f;
            #pragma unroll
            for (int w = 0; w < 16; w++) s += red[w];
            g_bt[t * 12 + hh] = 16.f / (1.f + expf(-s));
        }
        __syncthreads();
    }
}
__global__ void gather_kernel(const int* __restrict__ idx) {
    int e = blockIdx.x * 256 + threadIdx.x;
    if (e >= 12 * 49 * 49) return;
    int h = e / 2401, ij = e - h * 2401;
    g_rpb[e] = g_bt[idx[ij] * 12 + h];
}

// ---------------------------------------------------------------------------
// 3xTF32 warp-MMA GEMM: D[M,N] = A[M,384] @ B[N,384]^T, 128x128 block tile.
// A,B given as tf32 hi/lo pairs; per fragment: hi*hi + hi*lo + lo*hi.
// 8 warps as 2(m)x4(n), warp tile 64x32, k-chunk 32, double-buffered cp.async.
// mode 0: QKV (scatter into g_q/g_k/g_v with bias). mode 1: proj (+bias).
// ---------------------------------------------------------------------------
#define PITCH 36
#define TILE_F (128 * PITCH)
#define GEMM_SMEM (2 * 4 * TILE_F * 4)      // 2 stages x 4 comps x 18KB = 147456 B

__global__ void __launch_bounds__(256) gemm_mma(
    const float* __restrict__ Ahi, const float* __restrict__ Alo,
    const float* __restrict__ Bhi, const float* __restrict__ Blo, int mode,
    const float* __restrict__ bq, const float* __restrict__ bv,
    const float* __restrict__ bp, float* __restrict__ outp)
{
    extern __shared__ float sm[];
    int tid = threadIdx.x, wid = tid >> 5, lane = tid & 31;
    int g = lane >> 2, t = lane & 3;
    int m0 = blockIdx.x * 128, n0 = blockIdx.y * 128;
    int wm = (wid >> 2) * 64;
    int wn = (wid & 3) * 32;

    // smem: [stage][comp][TILE_F], comp: 0=Ahi 1=Alo 2=Bhi 3=Blo
    float c[4][4][4];
    #pragma unroll
    for (int mi = 0; mi < 4; mi++)
        #pragma unroll
        for (int nj = 0; nj < 4; nj++)
            #pragma unroll
            for (int r = 0; r < 4; r++) c[mi][nj][r] = 0.f;

    auto load_stage = [&](int it, int s) {
        int k0 = it * 32;
        uint32_t base = smem_u32(sm + s * 4 * TILE_F);
        #pragma unroll
        for (int q = 0; q < 4; q++) {
            int idx = q * 256 + tid;
            int r = idx >> 3, cc = idx & 7;
            uint32_t off = (uint32_t)(r * PITCH + cc * 4) * 4u;
            size_t ga = (size_t)(m0 + r) * 384 + k0 + cc * 4;
            size_t gb = (size_t)(n0 + r) * 384 + k0 + cc * 4;
            cp_async16(base + 0 * TILE_F * 4 + off, Ahi + ga);
            cp_async16(base + 1 * TILE_F * 4 + off, Alo + ga);
            cp_async16(base + 2 * TILE_F * 4 + off, Bhi + gb);
            cp_async16(base + 3 * TILE_F * 4 + off, Blo + gb);
        }
        CP_COMMIT();
    };

    load_stage(0, 0);
    load_stage(1, 1);

    for (int it = 0; it < 12; ++it) {
        int s = it & 1;
        cp_wait<1>();
        __syncthreads();
        const float* ah = sm + s * 4 * TILE_F;
        const float* al = ah + TILE_F;
        const float* bh = al + TILE_F;
        const float* bl = bh + TILE_F;
        #pragma unroll
        for (int kc = 0; kc < 32; kc += 8) {
            uint32_t ahf[4][4], alf[4][4], bhf[4][2], blf[4][2];
            #pragma unroll
            for (int mi = 0; mi < 4; mi++) {
                int rb = (wm + 16 * mi + g) * PITCH + kc + t;
                ahf[mi][0] = __float_as_uint(ah[rb]);
                ahf[mi][1] = __float_as_uint(ah[rb + 8 * PITCH]);
                ahf[mi][2] = __float_as_uint(ah[rb + 4]);
                ahf[mi][3] = __float_as_uint(ah[rb + 8 * PITCH + 4]);
                alf[mi][0] = __float_as_uint(al[rb]);
                alf[mi][1] = __float_as_uint(al[rb + 8 * PITCH]);
                alf[mi][2] = __float_as_uint(al[rb + 4]);
                alf[mi][3] = __float_as_uint(al[rb + 8 * PITCH + 4]);
            }
            #pragma unroll
            for (int nj = 0; nj < 4; nj++) {
                int rb = (wn + 8 * nj + g) * PITCH + kc + t;
                bhf[nj][0] = __float_as_uint(bh[rb]);
                bhf[nj][1] = __float_as_uint(bh[rb + 4]);
                blf[nj][0] = __float_as_uint(bl[rb]);
                blf[nj][1] = __float_as_uint(bl[rb + 4]);
            }
            #pragma unroll
            for (int mi = 0; mi < 4; mi++)
                #pragma unroll
                for (int nj = 0; nj < 4; nj++) {
                    mma_tf32(c[mi][nj][0], c[mi][nj][1], c[mi][nj][2], c[mi][nj][3],
                             ahf[mi][0], ahf[mi][1], ahf[mi][2], ahf[mi][3],
                             blf[nj][0], blf[nj][1]);
                    mma_tf32(c[mi][nj][0], c[mi][nj][1], c[mi][nj][2], c[mi][nj][3],
                             alf[mi][0], alf[mi][1], alf[mi][2], alf[mi][3],
                             bhf[nj][0], bhf[nj][1]);
                    mma_tf32(c[mi][nj][0], c[mi][nj][1], c[mi][nj][2], c[mi][nj][3],
                             ahf[mi][0], ahf[mi][1], ahf[mi][2], ahf[mi][3],
                             bhf[nj][0], bhf[nj][1]);
                }
        }
        __syncthreads();
        if (it + 2 < 12) load_stage(it + 2, s);
    }

    // Epilogue. c0,c1 -> row g, cols 2t,2t+1; c2,c3 -> row g+8.
    #pragma unroll
    for (int mi = 0; mi < 4; mi++) {
        #pragma unroll
        for (int half = 0; half < 2; half++) {
            int row = m0 + wm + 16 * mi + g + 8 * half;
            int b = row / 49, nn = row - b * 49;
            #pragma unroll
            for (int nj = 0; nj < 4; nj++) {
                int col = n0 + wn + 8 * nj + 2 * t;
                float2 v;
                v.x = c[mi][nj][2 * half + 0];
                v.y = c[mi][nj][2 * half + 1];
                if (mode == 0) {
                    int which = col / 384;
                    int rem = col - which * 384;
                    int h = rem >> 5, d = rem & 31;
                    if (which == 0)      { v.x += bq[rem]; v.y += bq[rem + 1]; }
                    else if (which == 2) { v.x += bv[rem]; v.y += bv[rem + 1]; }
                    float* dst = ((which == 0) ? g_q : (which == 1) ? g_k : g_v)
                                 + (((size_t)b * 12 + h) * 49 + nn) * 32 + d;
                    *(float2*)dst = v;
                } else {
                    v.x += bp[col]; v.y += bp[col + 1];
                    *(float2*)(outp + (size_t)row * 384 + col) = v;
                }
            }
        }
    }
}

// ---------------------------------------------------------------------------
// Attention: one block per (window b, head h). Writes hi/lo split of output.
// ---------------------------------------------------------------------------
__global__ void __launch_bounds__(256) attn_kernel(const float* __restrict__ mask,
                                                   const float* __restrict__ logit_scale)
{
    __shared__ float sq[49 * 32];
    __shared__ float sk[49 * 32];
    __shared__ float sv[49 * 32];
    __shared__ float sS[49 * 49];
    int bh = blockIdx.x;
    int b = bh / 12, h = bh - b * 12;
    int tid = threadIdx.x;

    size_t base = (size_t)bh * 49 * 32;
    for (int u = tid; u < 392; u += 256) {
        ((float4*)sq)[u] = ((const float4*)(g_q + base))[u];
        ((float4*)sk)[u] = ((const float4*)(g_k + base))[u];
        ((float4*)sv)[u] = ((const float4*)(g_v + base))[u];
    }
    __syncthreads();

    if (tid < 49) {
        float ss = 0.f;
        #pragma unroll
        for (int d = 0; d < 32; d++) { float x = sq[tid * 32 + d]; ss = fmaf(x, x, ss); }
        float sc = expf(fminf(logit_scale[h], 4.60517018598809136804f));
        float inv = sc / fmaxf(sqrtf(ss), 1e-12f);
        #pragma unroll
        for (int d = 0; d < 32; d++) sq[tid * 32 + d] *= inv;
    } else if (tid >= 64 && tid < 113) {
        int r = tid - 64;
        float ss = 0.f;
        #pragma unroll
        for (int d = 0; d < 32; d++) { float x = sk[r * 32 + d]; ss = fmaf(x, x, ss); }
        float inv = 1.f / fmaxf(sqrtf(ss), 1e-12f);
        #pragma unroll
        for (int d = 0; d < 32; d++) sk[r * 32 + d] *= inv;
    }
    __syncthreads();

    if (tid < 245) {
        int i = tid / 5, s5 = tid - i * 5;
        float4 qr[8];
        #pragma unroll
        for (int u = 0; u < 8; u++) qr[u] = ((const float4*)(sq + i * 32))[u];
        int j0 = s5 * 10;
        int j1 = j0 + 10 > 49 ? 49 : j0 + 10;
        for (int j = j0; j < j1; j++) {
            const float4* kr = (const float4*)(sk + j * 32);
            float accv = 0.f;
            #pragma unroll
            for (int u = 0; u < 8; u++) {
                float4 kv = kr[u];
                accv = fmaf(qr[u].x, kv.x, accv);
                accv = fmaf(qr[u].y, kv.y, accv);
                accv = fmaf(qr[u].z, kv.z, accv);
                accv = fmaf(qr[u].w, kv.w, accv);
            }
            sS[i * 49 + j] = accv;
        }
    }
    __syncthreads();

    if (tid < 49) {
        int i = tid;
        const float* rp = g_rpb + (h * 49 + i) * 49;
        const float* mp = mask + ((size_t)(b & 63) * 49 + i) * 49;
        float mx = -1e30f;
        for (int j = 0; j < 49; j++) {
            float s = sS[i * 49 + j] + rp[j] + mp[j];
            sS[i * 49 + j] = s;
            mx = fmaxf(mx, s);
        }
        float sum = 0.f;
        for (int j = 0; j < 49; j++) {
            float e = expf(sS[i * 49 + j] - mx);
            sS[i * 49 + j] = e;
            sum += e;
        }
        float inv = 1.f / sum;
        for (int j = 0; j < 49; j++) sS[i * 49 + j] *= inv;
    }
    __syncthreads();

    for (int e = tid; e < 49 * 32; e += 256) {
        int i = e >> 5, d = e & 31;
        float accv = 0.f;
        for (int j = 0; j < 49; j++)
            accv = fmaf(sS[i * 49 + j], sv[j * 32 + d], accv);
        size_t oidx = ((size_t)b * 49 + i) * 384 + h * 32 + d;
        float hi = tf32r(accv);
        g_ohi[oidx] = hi;
        g_olo[oidx] = tf32r(accv - hi);
    }
}

// ---------------------------------------------------------------------------
extern "C" void kernel_launch(void* const* d_in, const int* in_sizes, int n_in,
                              void* d_out, int out_size) {
    const float* x           = (const float*)d_in[0];
    const float* mask        = (const float*)d_in[1];
    const float* qkv_w       = (const float*)d_in[2];
    const float* q_bias      = (const float*)d_in[3];
    const float* v_bias      = (const float*)d_in[4];
    const float* logit_scale = (const float*)d_in[5];
    const float* cpb_w1      = (const float*)d_in[6];
    const float* cpb_b1      = (const float*)d_in[7];
    const float* cpb_w2      = (const float*)d_in[8];
    const float* proj_w      = (const float*)d_in[9];
    const float* proj_b      = (const float*)d_in[10];
    const float* table       = (const float*)d_in[11];
    const int*   idx         = (const int*)d_in[12];
    float* out = (float*)d_out;

    cudaFuncSetAttribute(gemm_mma, cudaFuncAttributeMaxDynamicSharedMemorySize, GEMM_SMEM);

    float *xhi, *xlo, *whi, *wlo, *phi, *plo, *ohi, *olo;
    cudaGetSymbolAddress((void**)&xhi, g_xhi);
    cudaGetSymbolAddress((void**)&xlo, g_xlo);
    cudaGetSymbolAddress((void**)&whi, g_whi);
    cudaGetSymbolAddress((void**)&wlo, g_wlo);
    cudaGetSymbolAddress((void**)&phi, g_phi);
    cudaGetSymbolAddress((void**)&plo, g_plo);
    cudaGetSymbolAddress((void**)&ohi, g_ohi);
    cudaGetSymbolAddress((void**)&olo, g_olo);

    split_kernel<<<(2048*49*384/4 + 255)/256, 256>>>(x, xhi, xlo, 2048*49*384/4);
    split_kernel<<<(1152*384/4 + 255)/256, 256>>>(qkv_w, whi, wlo, 1152*384/4);
    split_kernel<<<(384*384/4 + 255)/256, 256>>>(proj_w, phi, plo, 384*384/4);

    cpb_kernel<<<169, 512>>>(table, cpb_w1, cpb_b1, cpb_w2);
    gather_kernel<<<(12 * 2401 + 255) / 256, 256>>>(idx);

    gemm_mma<<<dim3(784, 9), 256, GEMM_SMEM>>>(xhi, xlo, whi, wlo, 0,
                                               q_bias, v_bias, nullptr, nullptr);
    attn_kernel<<<2048 * 12, 256>>>(mask, logit_scale);
    gemm_mma<<<dim3(784, 3), 256, GEMM_SMEM>>>(ohi, olo, phi, plo, 1,
                                               nullptr, nullptr, proj_b, out);
}

// round 5
// speedup vs baseline: 1.6993x; 1.2959x over previous
#include <cuda_runtime.h>
#include <cuda_bf16.h>
#include <math.h>
#include <stdint.h>

// B=2048 windows, N=49, C=384, H=12, hd=32, nW=64
__device__ float g_q  [2048u*12*49*32];
__device__ float g_k  [2048u*12*49*32];
__device__ float g_v  [2048u*12*49*32];
__device__ __nv_bfloat16 g_oh[2048u*49*384];  // attn out hi, [B][N][C]
__device__ __nv_bfloat16 g_ol[2048u*49*384];  // attn out lo
__device__ __nv_bfloat16 g_xh[2048u*49*384];
__device__ __nv_bfloat16 g_xl[2048u*49*384];
__device__ __nv_bfloat16 g_wh[1152*384];
__device__ __nv_bfloat16 g_wl[1152*384];
__device__ __nv_bfloat16 g_ph[384*384];
__device__ __nv_bfloat16 g_pl[384*384];
__device__ float g_bt [169*12];
__device__ float g_rpb[12*49*49];

// ---------------------------------------------------------------------------
__device__ __forceinline__ uint32_t smem_u32(const void* p) {
    uint32_t a;
    asm("{ .reg .u64 t; cvta.to.shared.u64 t, %1; cvt.u32.u64 %0, t; }" : "=r"(a) : "l"(p));
    return a;
}
__device__ __forceinline__ void cp_async16(uint32_t dst, const void* src) {
    asm volatile("cp.async.cg.shared.global [%0], [%1], 16;" :: "r"(dst), "l"(src));
}
#define CP_COMMIT() asm volatile("cp.async.commit_group;" ::: "memory")
template<int N> __device__ __forceinline__ void cp_wait() {
    asm volatile("cp.async.wait_group %0;" :: "n"(N) : "memory");
}
__device__ __forceinline__ void ldsm4(uint32_t& r0, uint32_t& r1, uint32_t& r2, uint32_t& r3,
                                      uint32_t addr) {
    asm volatile("ldmatrix.sync.aligned.m8n8.x4.shared.b16 {%0,%1,%2,%3}, [%4];"
                 : "=r"(r0), "=r"(r1), "=r"(r2), "=r"(r3) : "r"(addr));
}
__device__ __forceinline__ void mma_bf16(float& c0, float& c1, float& c2, float& c3,
                                         uint32_t a0, uint32_t a1, uint32_t a2, uint32_t a3,
                                         uint32_t b0, uint32_t b1) {
    asm volatile("mma.sync.aligned.m16n8k16.row.col.f32.bf16.bf16.f32 "
                 "{%0,%1,%2,%3}, {%4,%5,%6,%7}, {%8,%9}, {%0,%1,%2,%3};"
                 : "+f"(c0), "+f"(c1), "+f"(c2), "+f"(c3)
                 : "r"(a0), "r"(a1), "r"(a2), "r"(a3), "r"(b0), "r"(b1));
}

// ---------------------------------------------------------------------------
// bf16 hi/lo split prepass: hi = bf16(x), lo = bf16(x - hi)
// ---------------------------------------------------------------------------
__global__ void splitb_kernel(const float* __restrict__ in, __nv_bfloat16* __restrict__ hi,
                              __nv_bfloat16* __restrict__ lo, int n4) {
    int i = blockIdx.x * 256 + threadIdx.x;
    if (i >= n4) return;
    float4 v = ((const float4*)in)[i];
    float vv[4] = {v.x, v.y, v.z, v.w};
    __nv_bfloat16 h[4], l[4];
    #pragma unroll
    for (int j = 0; j < 4; j++) {
        h[j] = __float2bfloat16(vv[j]);
        l[j] = __float2bfloat16(vv[j] - __bfloat162float(h[j]));
    }
    ((__nv_bfloat162*)hi)[2*i]   = __nv_bfloat162{h[0], h[1]};
    ((__nv_bfloat162*)hi)[2*i+1] = __nv_bfloat162{h[2], h[3]};
    ((__nv_bfloat162*)lo)[2*i]   = __nv_bfloat162{l[0], l[1]};
    ((__nv_bfloat162*)lo)[2*i+1] = __nv_bfloat162{l[2], l[3]};
}

// ---------------------------------------------------------------------------
// CPB MLP + gather
// ---------------------------------------------------------------------------
__global__ void cpb_kernel(const float* __restrict__ table, const float* __restrict__ w1,
                           const float* __restrict__ b1, const float* __restrict__ w2) {
    __shared__ float red[16];
    int t = blockIdx.x, j = threadIdx.x;
    float t0 = table[t * 2 + 0], t1 = table[t * 2 + 1];
    float h = fmaxf(fmaf(t0, w1[j * 2 + 0], fmaf(t1, w1[j * 2 + 1], b1[j])), 0.f);
    for (int hh = 0; hh < 12; hh++) {
        float v = h * w2[hh * 512 + j];
        #pragma unroll
        for (int o = 16; o > 0; o >>= 1) v += __shfl_down_sync(0xffffffffu, v, o);
        if ((j & 31) == 0) red[j >> 5] = v;
        __syncthreads();
        if (j == 0) {
            float s = 0.f;
            #pragma unroll
            for (int w = 0; w < 16; w++) s += red[w];
            g_bt[t * 12 + hh] = 16.f / (1.f + expf(-s));
        }
        __syncthreads();
    }
}
__global__ void gather_kernel(const int* __restrict__ idx) {
    int e = blockIdx.x * 256 + threadIdx.x;
    if (e >= 12 * 49 * 49) return;
    int h = e / 2401, ij = e - h * 2401;
    g_rpb[e] = g_bt[idx[ij] * 12 + h];
}

// ---------------------------------------------------------------------------
// 3xBF16 warp-MMA GEMM: D[M,N] = A[M,384] @ B[N,384]^T, 128x128 block tile.
// A,B as bf16 hi/lo pairs; per fragment: hi*hi + hi*lo + lo*hi, fp32 accum.
// 8 warps 2(m)x4(n), warp tile 64x32, k-chunk 32 (2x k16 MMA), ldmatrix loads.
// mode 0: QKV (scatter into g_q/g_k/g_v with bias). mode 1: proj (+bias).
// ---------------------------------------------------------------------------
#define PITCHE 40                       // bf16 elements per smem row (80B)
#define COMP_B (128 * PITCHE * 2)       // bytes per component tile = 10240
#define STAGE_B (4 * COMP_B)            // 40960
#define GEMM_SMEM (2 * STAGE_B)         // 81920

__global__ void __launch_bounds__(256) gemm_mma(
    const __nv_bfloat16* __restrict__ Ahi, const __nv_bfloat16* __restrict__ Alo,
    const __nv_bfloat16* __restrict__ Bhi, const __nv_bfloat16* __restrict__ Blo, int mode,
    const float* __restrict__ bq, const float* __restrict__ bv,
    const float* __restrict__ bp, float* __restrict__ outp)
{
    extern __shared__ char sm[];
    uint32_t sbase = smem_u32(sm);
    int tid = threadIdx.x, wid = tid >> 5, lane = tid & 31;
    int g = lane >> 2, t = lane & 3;
    int grp = lane >> 3, rin = lane & 7;
    int m0 = blockIdx.x * 128, n0 = blockIdx.y * 128;
    int wm = (wid >> 2) * 64;
    int wn = (wid & 3) * 32;

    float c[4][4][4];
    #pragma unroll
    for (int mi = 0; mi < 4; mi++)
        #pragma unroll
        for (int nj = 0; nj < 4; nj++)
            #pragma unroll
            for (int r = 0; r < 4; r++) c[mi][nj][r] = 0.f;

    // ldmatrix element offsets (add kc, scale by 2 for bytes)
    int aoff[4], boff[2];
    #pragma unroll
    for (int mi = 0; mi < 4; mi++)
        aoff[mi] = (wm + 16 * mi + (grp & 1) * 8 + rin) * PITCHE + (grp >> 1) * 8;
    #pragma unroll
    for (int j = 0; j < 2; j++)
        boff[j] = (wn + 16 * j + (grp >> 1) * 8 + rin) * PITCHE + (grp & 1) * 8;

    auto load_stage = [&](int it, int s) {
        int k0 = it * 32;
        uint32_t sb = sbase + s * STAGE_B;
        #pragma unroll
        for (int q = 0; q < 2; q++) {
            int cc = q * 256 + tid;
            int r = cc >> 2, seg = cc & 3;
            uint32_t off = (uint32_t)(r * (PITCHE * 2) + seg * 16);
            size_t ga = (size_t)(m0 + r) * 384 + k0 + seg * 8;
            size_t gb = (size_t)(n0 + r) * 384 + k0 + seg * 8;
            cp_async16(sb + 0 * COMP_B + off, Ahi + ga);
            cp_async16(sb + 1 * COMP_B + off, Alo + ga);
            cp_async16(sb + 2 * COMP_B + off, Bhi + gb);
            cp_async16(sb + 3 * COMP_B + off, Blo + gb);
        }
        CP_COMMIT();
    };

    load_stage(0, 0);
    load_stage(1, 1);

    for (int it = 0; it < 12; ++it) {
        int s = it & 1;
        cp_wait<1>();
        __syncthreads();
        uint32_t sb = sbase + s * STAGE_B;
        #pragma unroll
        for (int kc = 0; kc < 32; kc += 16) {
            uint32_t ah[4][4], al[4][4], bh[2][4], bl[2][4];
            #pragma unroll
            for (int mi = 0; mi < 4; mi++) {
                uint32_t ao = sb + (uint32_t)((aoff[mi] + kc) * 2);
                ldsm4(ah[mi][0], ah[mi][1], ah[mi][2], ah[mi][3], ao + 0 * COMP_B);
                ldsm4(al[mi][0], al[mi][1], al[mi][2], al[mi][3], ao + 1 * COMP_B);
            }
            #pragma unroll
            for (int j = 0; j < 2; j++) {
                uint32_t bo = sb + (uint32_t)((boff[j] + kc) * 2);
                ldsm4(bh[j][0], bh[j][1], bh[j][2], bh[j][3], bo + 2 * COMP_B);
                ldsm4(bl[j][0], bl[j][1], bl[j][2], bl[j][3], bo + 3 * COMP_B);
            }
            #pragma unroll
            for (int mi = 0; mi < 4; mi++)
                #pragma unroll
                for (int nj = 0; nj < 4; nj++) {
                    int j = nj >> 1, hf = (nj & 1) * 2;
                    mma_bf16(c[mi][nj][0], c[mi][nj][1], c[mi][nj][2], c[mi][nj][3],
                             ah[mi][0], ah[mi][1], ah[mi][2], ah[mi][3],
                             bl[j][hf], bl[j][hf + 1]);
                    mma_bf16(c[mi][nj][0], c[mi][nj][1], c[mi][nj][2], c[mi][nj][3],
                             al[mi][0], al[mi][1], al[mi][2], al[mi][3],
                             bh[j][hf], bh[j][hf + 1]);
                    mma_bf16(c[mi][nj][0], c[mi][nj][1], c[mi][nj][2], c[mi][nj][3],
                             ah[mi][0], ah[mi][1], ah[mi][2], ah[mi][3],
                             bh[j][hf], bh[j][hf + 1]);
                }
        }
        __syncthreads();
        if (it + 2 < 12) load_stage(it + 2, s);
    }

    // Epilogue: c0,c1 -> row g, cols 2t,2t+1; c2,c3 -> row g+8.
    #pragma unroll
    for (int mi = 0; mi < 4; mi++) {
        #pragma unroll
        for (int half = 0; half < 2; half++) {
            int row = m0 + wm + 16 * mi + g + 8 * half;
            int b = row / 49, nn = row - b * 49;
            #pragma unroll
            for (int nj = 0; nj < 4; nj++) {
                int col = n0 + wn + 8 * nj + 2 * t;
                float2 v;
                v.x = c[mi][nj][2 * half + 0];
                v.y = c[mi][nj][2 * half + 1];
                if (mode == 0) {
                    int which = col / 384;
                    int rem = col - which * 384;
                    int h = rem >> 5, d = rem & 31;
                    if (which == 0)      { v.x += bq[rem]; v.y += bq[rem + 1]; }
                    else if (which == 2) { v.x += bv[rem]; v.y += bv[rem + 1]; }
                    float* dst = ((which == 0) ? g_q : (which == 1) ? g_k : g_v)
                                 + (((size_t)b * 12 + h) * 49 + nn) * 32 + d;
                    *(float2*)dst = v;
                } else {
                    v.x += bp[col]; v.y += bp[col + 1];
                    *(float2*)(outp + (size_t)row * 384 + col) = v;
                }
            }
        }
    }
}

// ---------------------------------------------------------------------------
// Attention: one block per (window b, head h). Writes bf16 hi/lo split.
// ---------------------------------------------------------------------------
__global__ void __launch_bounds__(256) attn_kernel(const float* __restrict__ mask,
                                                   const float* __restrict__ logit_scale)
{
    __shared__ float sq[49 * 32];
    __shared__ float sk[49 * 32];
    __shared__ float sv[49 * 32];
    __shared__ float sS[49 * 49];
    int bh = blockIdx.x;
    int b = bh / 12, h = bh - b * 12;
    int tid = threadIdx.x;

    size_t base = (size_t)bh * 49 * 32;
    for (int u = tid; u < 392; u += 256) {
        ((float4*)sq)[u] = ((const float4*)(g_q + base))[u];
        ((float4*)sk)[u] = ((const float4*)(g_k + base))[u];
        ((float4*)sv)[u] = ((const float4*)(g_v + base))[u];
    }
    __syncthreads();

    if (tid < 49) {
        float ss = 0.f;
        #pragma unroll
        for (int d = 0; d < 32; d++) { float x = sq[tid * 32 + d]; ss = fmaf(x, x, ss); }
        float sc = expf(fminf(logit_scale[h], 4.60517018598809136804f));
        float inv = sc / fmaxf(sqrtf(ss), 1e-12f);
        #pragma unroll
        for (int d = 0; d < 32; d++) sq[tid * 32 + d] *= inv;
    } else if (tid >= 64 && tid < 113) {
        int r = tid - 64;
        float ss = 0.f;
        #pragma unroll
        for (int d = 0; d < 32; d++) { float x = sk[r * 32 + d]; ss = fmaf(x, x, ss); }
        float inv = 1.f / fmaxf(sqrtf(ss), 1e-12f);
        #pragma unroll
        for (int d = 0; d < 32; d++) sk[r * 32 + d] *= inv;
    }
    __syncthreads();

    if (tid < 245) {
        int i = tid / 5, s5 = tid - i * 5;
        float4 qr[8];
        #pragma unroll
        for (int u = 0; u < 8; u++) qr[u] = ((const float4*)(sq + i * 32))[u];
        int j0 = s5 * 10;
        int j1 = j0 + 10 > 49 ? 49 : j0 + 10;
        for (int j = j0; j < j1; j++) {
            const float4* kr = (const float4*)(sk + j * 32);
            float accv = 0.f;
            #pragma unroll
            for (int u = 0; u < 8; u++) {
                float4 kv = kr[u];
                accv = fmaf(qr[u].x, kv.x, accv);
                accv = fmaf(qr[u].y, kv.y, accv);
                accv = fmaf(qr[u].z, kv.z, accv);
                accv = fmaf(qr[u].w, kv.w, accv);
            }
            sS[i * 49 + j] = accv;
        }
    }
    __syncthreads();

    if (tid < 49) {
        int i = tid;
        const float* rp = g_rpb + (h * 49 + i) * 49;
        const float* mp = mask + ((size_t)(b & 63) * 49 + i) * 49;
        float mx = -1e30f;
        for (int j = 0; j < 49; j++) {
            float s = sS[i * 49 + j] + rp[j] + mp[j];
            sS[i * 49 + j] = s;
            mx = fmaxf(mx, s);
        }
        float sum = 0.f;
        for (int j = 0; j < 49; j++) {
            float e = expf(sS[i * 49 + j] - mx);
            sS[i * 49 + j] = e;
            sum += e;
        }
        float inv = 1.f / sum;
        for (int j = 0; j < 49; j++) sS[i * 49 + j] *= inv;
    }
    __syncthreads();

    for (int e = tid; e < 49 * 32; e += 256) {
        int i = e >> 5, d = e & 31;
        float accv = 0.f;
        for (int j = 0; j < 49; j++)
            accv = fmaf(sS[i * 49 + j], sv[j * 32 + d], accv);
        size_t oidx = ((size_t)b * 49 + i) * 384 + h * 32 + d;
        __nv_bfloat16 hi = __float2bfloat16(accv);
        g_oh[oidx] = hi;
        g_ol[oidx] = __float2bfloat16(accv - __bfloat162float(hi));
    }
}

// ---------------------------------------------------------------------------
extern "C" void kernel_launch(void* const* d_in, const int* in_sizes, int n_in,
                              void* d_out, int out_size) {
    const float* x           = (const float*)d_in[0];
    const float* mask        = (const float*)d_in[1];
    const float* qkv_w       = (const float*)d_in[2];
    const float* q_bias      = (const float*)d_in[3];
    const float* v_bias      = (const float*)d_in[4];
    const float* logit_scale = (const float*)d_in[5];
    const float* cpb_w1      = (const float*)d_in[6];
    const float* cpb_b1      = (const float*)d_in[7];
    const float* cpb_w2      = (const float*)d_in[8];
    const float* proj_w      = (const float*)d_in[9];
    const float* proj_b      = (const float*)d_in[10];
    const float* table       = (const float*)d_in[11];
    const int*   idx         = (const int*)d_in[12];
    float* out = (float*)d_out;

    cudaFuncSetAttribute(gemm_mma, cudaFuncAttributeMaxDynamicSharedMemorySize, GEMM_SMEM);

    __nv_bfloat16 *xh, *xl, *wh, *wl, *ph, *pl, *oh, *ol;
    cudaGetSymbolAddress((void**)&xh, g_xh);
    cudaGetSymbolAddress((void**)&xl, g_xl);
    cudaGetSymbolAddress((void**)&wh, g_wh);
    cudaGetSymbolAddress((void**)&wl, g_wl);
    cudaGetSymbolAddress((void**)&ph, g_ph);
    cudaGetSymbolAddress((void**)&pl, g_pl);
    cudaGetSymbolAddress((void**)&oh, g_oh);
    cudaGetSymbolAddress((void**)&ol, g_ol);

    splitb_kernel<<<(2048*49*384/4 + 255)/256, 256>>>(x, xh, xl, 2048*49*384/4);
    splitb_kernel<<<(1152*384/4 + 255)/256, 256>>>(qkv_w, wh, wl, 1152*384/4);
    splitb_kernel<<<(384*384/4 + 255)/256, 256>>>(proj_w, ph, pl, 384*384/4);

    cpb_kernel<<<169, 512>>>(table, cpb_w1, cpb_b1, cpb_w2);
    gather_kernel<<<(12 * 2401 + 255) / 256, 256>>>(idx);

    gemm_mma<<<dim3(784, 9), 256, GEMM_SMEM>>>(xh, xl, wh, wl, 0,
                                               q_bias, v_bias, nullptr, nullptr);
    attn_kernel<<<2048 * 12, 256>>>(mask, logit_scale);
    gemm_mma<<<dim3(784, 3), 256, GEMM_SMEM>>>(oh, ol, ph, pl, 1,
                                               nullptr, nullptr, proj_b, out);
}

// round 6
// speedup vs baseline: 2.3642x; 1.3913x over previous
#include <cuda_runtime.h>
#include <cuda_bf16.h>
#include <math.h>
#include <stdint.h>

// B=2048 windows, N=49, C=384, H=12, hd=32, nW=64
__device__ float g_q  [2048u*12*49*32];
__device__ float g_k  [2048u*12*49*32];
__device__ float g_v  [2048u*12*49*32];
__device__ __nv_bfloat16 g_oh[2048u*49*384];  // attn out hi, [B][N][C]
__device__ __nv_bfloat16 g_ol[2048u*49*384];  // attn out lo
__device__ __nv_bfloat16 g_xh[2048u*49*384];
__device__ __nv_bfloat16 g_xl[2048u*49*384];
__device__ __nv_bfloat16 g_wh[1152*384];
__device__ __nv_bfloat16 g_wl[1152*384];
__device__ __nv_bfloat16 g_ph[384*384];
__device__ __nv_bfloat16 g_pl[384*384];
__device__ float g_bt [169*12];
__device__ float g_rpb[12*49*49];

// ---------------------------------------------------------------------------
__device__ __forceinline__ uint32_t smem_u32(const void* p) {
    uint32_t a;
    asm("{ .reg .u64 t; cvta.to.shared.u64 t, %1; cvt.u32.u64 %0, t; }" : "=r"(a) : "l"(p));
    return a;
}
__device__ __forceinline__ void cp_async16(uint32_t dst, const void* src) {
    asm volatile("cp.async.cg.shared.global [%0], [%1], 16;" :: "r"(dst), "l"(src));
}
#define CP_COMMIT() asm volatile("cp.async.commit_group;" ::: "memory")
template<int N> __device__ __forceinline__ void cp_wait() {
    asm volatile("cp.async.wait_group %0;" :: "n"(N) : "memory");
}
__device__ __forceinline__ void ldsm4(uint32_t& r0, uint32_t& r1, uint32_t& r2, uint32_t& r3,
                                      uint32_t addr) {
    asm volatile("ldmatrix.sync.aligned.m8n8.x4.shared.b16 {%0,%1,%2,%3}, [%4];"
                 : "=r"(r0), "=r"(r1), "=r"(r2), "=r"(r3) : "r"(addr));
}
__device__ __forceinline__ void mma_bf16(float& c0, float& c1, float& c2, float& c3,
                                         uint32_t a0, uint32_t a1, uint32_t a2, uint32_t a3,
                                         uint32_t b0, uint32_t b1) {
    asm volatile("mma.sync.aligned.m16n8k16.row.col.f32.bf16.bf16.f32 "
                 "{%0,%1,%2,%3}, {%4,%5,%6,%7}, {%8,%9}, {%0,%1,%2,%3};"
                 : "+f"(c0), "+f"(c1), "+f"(c2), "+f"(c3)
                 : "r"(a0), "r"(a1), "r"(a2), "r"(a3), "r"(b0), "r"(b1));
}

// ---------------------------------------------------------------------------
// bf16 hi/lo split prepass
// ---------------------------------------------------------------------------
__global__ void splitb_kernel(const float* __restrict__ in, __nv_bfloat16* __restrict__ hi,
                              __nv_bfloat16* __restrict__ lo, int n4) {
    int i = blockIdx.x * 256 + threadIdx.x;
    if (i >= n4) return;
    float4 v = ((const float4*)in)[i];
    float vv[4] = {v.x, v.y, v.z, v.w};
    __nv_bfloat16 h[4], l[4];
    #pragma unroll
    for (int j = 0; j < 4; j++) {
        h[j] = __float2bfloat16(vv[j]);
        l[j] = __float2bfloat16(vv[j] - __bfloat162float(h[j]));
    }
    ((__nv_bfloat162*)hi)[2*i]   = __nv_bfloat162{h[0], h[1]};
    ((__nv_bfloat162*)hi)[2*i+1] = __nv_bfloat162{h[2], h[3]};
    ((__nv_bfloat162*)lo)[2*i]   = __nv_bfloat162{l[0], l[1]};
    ((__nv_bfloat162*)lo)[2*i+1] = __nv_bfloat162{l[2], l[3]};
}

// ---------------------------------------------------------------------------
// CPB MLP + gather
// ---------------------------------------------------------------------------
__global__ void cpb_kernel(const float* __restrict__ table, const float* __restrict__ w1,
                           const float* __restrict__ b1, const float* __restrict__ w2) {
    __shared__ float red[16];
    int t = blockIdx.x, j = threadIdx.x;
    float t0 = table[t * 2 + 0], t1 = table[t * 2 + 1];
    float h = fmaxf(fmaf(t0, w1[j * 2 + 0], fmaf(t1, w1[j * 2 + 1], b1[j])), 0.f);
    for (int hh = 0; hh < 12; hh++) {
        float v = h * w2[hh * 512 + j];
        #pragma unroll
        for (int o = 16; o > 0; o >>= 1) v += __shfl_down_sync(0xffffffffu, v, o);
        if ((j & 31) == 0) red[j >> 5] = v;
        __syncthreads();
        if (j == 0) {
            float s = 0.f;
            #pragma unroll
            for (int w = 0; w < 16; w++) s += red[w];
            g_bt[t * 12 + hh] = 16.f / (1.f + expf(-s));
        }
        __syncthreads();
    }
}
__global__ void gather_kernel(const int* __restrict__ idx) {
    int e = blockIdx.x * 256 + threadIdx.x;
    if (e >= 12 * 49 * 49) return;
    int h = e / 2401, ij = e - h * 2401;
    g_rpb[e] = g_bt[idx[ij] * 12 + h];
}

// ---------------------------------------------------------------------------
// 3xBF16 warp-MMA GEMM (unchanged from round 5)
// ---------------------------------------------------------------------------
#define PITCHE 40
#define COMP_B (128 * PITCHE * 2)
#define STAGE_B (4 * COMP_B)
#define GEMM_SMEM (2 * STAGE_B)

__global__ void __launch_bounds__(256) gemm_mma(
    const __nv_bfloat16* __restrict__ Ahi, const __nv_bfloat16* __restrict__ Alo,
    const __nv_bfloat16* __restrict__ Bhi, const __nv_bfloat16* __restrict__ Blo, int mode,
    const float* __restrict__ bq, const float* __restrict__ bv,
    const float* __restrict__ bp, float* __restrict__ outp)
{
    extern __shared__ char sm[];
    uint32_t sbase = smem_u32(sm);
    int tid = threadIdx.x, wid = tid >> 5, lane = tid & 31;
    int g = lane >> 2, t = lane & 3;
    int grp = lane >> 3, rin = lane & 7;
    int m0 = blockIdx.x * 128, n0 = blockIdx.y * 128;
    int wm = (wid >> 2) * 64;
    int wn = (wid & 3) * 32;

    float c[4][4][4];
    #pragma unroll
    for (int mi = 0; mi < 4; mi++)
        #pragma unroll
        for (int nj = 0; nj < 4; nj++)
            #pragma unroll
            for (int r = 0; r < 4; r++) c[mi][nj][r] = 0.f;

    int aoff[4], boff[2];
    #pragma unroll
    for (int mi = 0; mi < 4; mi++)
        aoff[mi] = (wm + 16 * mi + (grp & 1) * 8 + rin) * PITCHE + (grp >> 1) * 8;
    #pragma unroll
    for (int j = 0; j < 2; j++)
        boff[j] = (wn + 16 * j + (grp >> 1) * 8 + rin) * PITCHE + (grp & 1) * 8;

    auto load_stage = [&](int it, int s) {
        int k0 = it * 32;
        uint32_t sb = sbase + s * STAGE_B;
        #pragma unroll
        for (int q = 0; q < 2; q++) {
            int cc = q * 256 + tid;
            int r = cc >> 2, seg = cc & 3;
            uint32_t off = (uint32_t)(r * (PITCHE * 2) + seg * 16);
            size_t ga = (size_t)(m0 + r) * 384 + k0 + seg * 8;
            size_t gb = (size_t)(n0 + r) * 384 + k0 + seg * 8;
            cp_async16(sb + 0 * COMP_B + off, Ahi + ga);
            cp_async16(sb + 1 * COMP_B + off, Alo + ga);
            cp_async16(sb + 2 * COMP_B + off, Bhi + gb);
            cp_async16(sb + 3 * COMP_B + off, Blo + gb);
        }
        CP_COMMIT();
    };

    load_stage(0, 0);
    load_stage(1, 1);

    for (int it = 0; it < 12; ++it) {
        int s = it & 1;
        cp_wait<1>();
        __syncthreads();
        uint32_t sb = sbase + s * STAGE_B;
        #pragma unroll
        for (int kc = 0; kc < 32; kc += 16) {
            uint32_t ah[4][4], al[4][4], bh[2][4], bl[2][4];
            #pragma unroll
            for (int mi = 0; mi < 4; mi++) {
                uint32_t ao = sb + (uint32_t)((aoff[mi] + kc) * 2);
                ldsm4(ah[mi][0], ah[mi][1], ah[mi][2], ah[mi][3], ao + 0 * COMP_B);
                ldsm4(al[mi][0], al[mi][1], al[mi][2], al[mi][3], ao + 1 * COMP_B);
            }
            #pragma unroll
            for (int j = 0; j < 2; j++) {
                uint32_t bo = sb + (uint32_t)((boff[j] + kc) * 2);
                ldsm4(bh[j][0], bh[j][1], bh[j][2], bh[j][3], bo + 2 * COMP_B);
                ldsm4(bl[j][0], bl[j][1], bl[j][2], bl[j][3], bo + 3 * COMP_B);
            }
            #pragma unroll
            for (int mi = 0; mi < 4; mi++)
                #pragma unroll
                for (int nj = 0; nj < 4; nj++) {
                    int j = nj >> 1, hf = (nj & 1) * 2;
                    mma_bf16(c[mi][nj][0], c[mi][nj][1], c[mi][nj][2], c[mi][nj][3],
                             ah[mi][0], ah[mi][1], ah[mi][2], ah[mi][3],
                             bl[j][hf], bl[j][hf + 1]);
                    mma_bf16(c[mi][nj][0], c[mi][nj][1], c[mi][nj][2], c[mi][nj][3],
                             al[mi][0], al[mi][1], al[mi][2], al[mi][3],
                             bh[j][hf], bh[j][hf + 1]);
                    mma_bf16(c[mi][nj][0], c[mi][nj][1], c[mi][nj][2], c[mi][nj][3],
                             ah[mi][0], ah[mi][1], ah[mi][2], ah[mi][3],
                             bh[j][hf], bh[j][hf + 1]);
                }
        }
        __syncthreads();
        if (it + 2 < 12) load_stage(it + 2, s);
    }

    #pragma unroll
    for (int mi = 0; mi < 4; mi++) {
        #pragma unroll
        for (int half = 0; half < 2; half++) {
            int row = m0 + wm + 16 * mi + g + 8 * half;
            int b = row / 49, nn = row - b * 49;
            #pragma unroll
            for (int nj = 0; nj < 4; nj++) {
                int col = n0 + wn + 8 * nj + 2 * t;
                float2 v;
                v.x = c[mi][nj][2 * half + 0];
                v.y = c[mi][nj][2 * half + 1];
                if (mode == 0) {
                    int which = col / 384;
                    int rem = col - which * 384;
                    int h = rem >> 5, d = rem & 31;
                    if (which == 0)      { v.x += bq[rem]; v.y += bq[rem + 1]; }
                    else if (which == 2) { v.x += bv[rem]; v.y += bv[rem + 1]; }
                    float* dst = ((which == 0) ? g_q : (which == 1) ? g_k : g_v)
                                 + (((size_t)b * 12 + h) * 49 + nn) * 32 + d;
                    *(float2*)dst = v;
                } else {
                    v.x += bp[col]; v.y += bp[col + 1];
                    *(float2*)(outp + (size_t)row * 384 + col) = v;
                }
            }
        }
    }
}

// ---------------------------------------------------------------------------
// Attention v2: one block per (b,h). Pitch-36 smem, tiled S/PV, parallel softmax.
// ---------------------------------------------------------------------------
#define QP 36
#define SP 50

__global__ void __launch_bounds__(256) attn_kernel(const float* __restrict__ mask,
                                                   const float* __restrict__ logit_scale)
{
    __shared__ float sq[49 * QP];
    __shared__ float sk[49 * QP];
    __shared__ float sv[49 * QP];
    __shared__ float sS[49 * SP];
    __shared__ float sredA[245];
    __shared__ float sredB[245];
    int bh = blockIdx.x;
    int b = bh / 12, h = bh - b * 12;
    int tid = threadIdx.x;

    size_t base = (size_t)bh * 49 * 32;
    const float4* gq4 = (const float4*)(g_q + base);
    const float4* gk4 = (const float4*)(g_k + base);
    const float4* gv4 = (const float4*)(g_v + base);
    for (int u = tid; u < 392; u += 256) {
        int r = u >> 3, c4 = (u & 7) * 4;
        *(float4*)(sq + r * QP + c4) = gq4[u];
        *(float4*)(sk + r * QP + c4) = gk4[u];
        *(float4*)(sv + r * QP + c4) = gv4[u];
    }
    __syncthreads();

    // normalize q (with logit scale) and k
    if (tid < 98) {
        int r = (tid < 49) ? tid : tid - 49;
        float* s = (tid < 49) ? sq : sk;
        float ss = 0.f;
        #pragma unroll
        for (int d = 0; d < 32; d++) { float x = s[r * QP + d]; ss = fmaf(x, x, ss); }
        float inv = 1.f / fmaxf(sqrtf(ss), 1e-12f);
        if (tid < 49) inv *= expf(fminf(logit_scale[h], 4.60517018598809136804f));
        #pragma unroll
        for (int d = 0; d < 32; d++) s[r * QP + d] *= inv;
    }
    __syncthreads();

    // S = qn @ kn^T : 125 threads, 2-row x 5-colgroup tiles, q rows in regs
    if (tid < 125) {
        int ip = tid / 5, jg = tid - ip * 5;
        int i0 = ip * 2, i1 = i0 + 1;
        bool has1 = (i1 < 49);
        float4 qa[8], qb[8];
        #pragma unroll
        for (int u = 0; u < 8; u++) qa[u] = *(const float4*)(sq + i0 * QP + u * 4);
        if (has1) {
            #pragma unroll
            for (int u = 0; u < 8; u++) qb[u] = *(const float4*)(sq + i1 * QP + u * 4);
        }
        #pragma unroll
        for (int jj = 0; jj < 10; jj++) {
            int j = jg * 10 + jj;
            if (j >= 49) break;
            float a0 = 0.f, a1 = 0.f;
            #pragma unroll
            for (int u = 0; u < 8; u++) {
                float4 kv = *(const float4*)(sk + j * QP + u * 4);
                a0 = fmaf(qa[u].x, kv.x, a0); a0 = fmaf(qa[u].y, kv.y, a0);
                a0 = fmaf(qa[u].z, kv.z, a0); a0 = fmaf(qa[u].w, kv.w, a0);
                if (has1) {
                    a1 = fmaf(qb[u].x, kv.x, a1); a1 = fmaf(qb[u].y, kv.y, a1);
                    a1 = fmaf(qb[u].z, kv.z, a1); a1 = fmaf(qb[u].w, kv.w, a1);
                }
            }
            sS[i0 * SP + j] = a0;
            if (has1) sS[i1 * SP + j] = a1;
        }
    }
    __syncthreads();

    // softmax: 245 threads, 5 per row x 10 cols, two-stage reductions
    int si = tid / 5, sp = tid - si * 5;
    int j0 = sp * 10, j1 = min(j0 + 10, 49);
    if (tid < 245) {
        const float* rp = g_rpb + (h * 49 + si) * 49;
        const float* mp = mask + ((size_t)(b & 63) * 49 + si) * 49;
        float lmax = -1e30f;
        for (int j = j0; j < j1; j++) {
            float s = sS[si * SP + j] + rp[j] + mp[j];
            sS[si * SP + j] = s;
            lmax = fmaxf(lmax, s);
        }
        sredA[tid] = lmax;
    }
    __syncthreads();
    if (tid < 245) {
        float mx = sredA[si * 5];
        #pragma unroll
        for (int p = 1; p < 5; p++) mx = fmaxf(mx, sredA[si * 5 + p]);
        float lsum = 0.f;
        for (int j = j0; j < j1; j++) {
            float e = expf(sS[si * SP + j] - mx);
            sS[si * SP + j] = e;
            lsum += e;
        }
        sredB[tid] = lsum;
    }
    __syncthreads();
    if (tid < 245) {
        float sum = sredB[si * 5];
        #pragma unroll
        for (int p = 1; p < 5; p++) sum += sredB[si * 5 + p];
        float inv = 1.f / sum;
        for (int j = j0; j < j1; j++) sS[si * SP + j] *= inv;
    }
    __syncthreads();

    // PV: 104 threads, 4-row x 4-col tiles; out = P @ V -> bf16 hi/lo
    if (tid < 104) {
        int ipart = tid >> 3, dq = tid & 7;
        int r0 = ipart * 4;
        float4 acc[4] = {{0,0,0,0},{0,0,0,0},{0,0,0,0},{0,0,0,0}};
        for (int j = 0; j < 49; j++) {
            float4 v = *(const float4*)(sv + j * QP + dq * 4);
            #pragma unroll
            for (int rr = 0; rr < 4; rr++) {
                int r = r0 + rr;
                float s = (r < 49) ? sS[r * SP + j] : 0.f;
                acc[rr].x = fmaf(s, v.x, acc[rr].x);
                acc[rr].y = fmaf(s, v.y, acc[rr].y);
                acc[rr].z = fmaf(s, v.z, acc[rr].z);
                acc[rr].w = fmaf(s, v.w, acc[rr].w);
            }
        }
        #pragma unroll
        for (int rr = 0; rr < 4; rr++) {
            int r = r0 + rr;
            if (r < 49) {
                size_t oidx = ((size_t)b * 49 + r) * 384 + h * 32 + dq * 4;
                float av[4] = {acc[rr].x, acc[rr].y, acc[rr].z, acc[rr].w};
                __nv_bfloat16 hh[4], ll[4];
                #pragma unroll
                for (int e = 0; e < 4; e++) {
                    hh[e] = __float2bfloat16(av[e]);
                    ll[e] = __float2bfloat16(av[e] - __bfloat162float(hh[e]));
                }
                *(__nv_bfloat162*)(g_oh + oidx)     = __nv_bfloat162{hh[0], hh[1]};
                *(__nv_bfloat162*)(g_oh + oidx + 2) = __nv_bfloat162{hh[2], hh[3]};
                *(__nv_bfloat162*)(g_ol + oidx)     = __nv_bfloat162{ll[0], ll[1]};
                *(__nv_bfloat162*)(g_ol + oidx + 2) = __nv_bfloat162{ll[2], ll[3]};
            }
        }
    }
}

// ---------------------------------------------------------------------------
extern "C" void kernel_launch(void* const* d_in, const int* in_sizes, int n_in,
                              void* d_out, int out_size) {
    const float* x           = (const float*)d_in[0];
    const float* mask        = (const float*)d_in[1];
    const float* qkv_w       = (const float*)d_in[2];
    const float* q_bias      = (const float*)d_in[3];
    const float* v_bias      = (const float*)d_in[4];
    const float* logit_scale = (const float*)d_in[5];
    const float* cpb_w1      = (const float*)d_in[6];
    const float* cpb_b1      = (const float*)d_in[7];
    const float* cpb_w2      = (const float*)d_in[8];
    const float* proj_w      = (const float*)d_in[9];
    const float* proj_b      = (const float*)d_in[10];
    const float* table       = (const float*)d_in[11];
    const int*   idx         = (const int*)d_in[12];
    float* out = (float*)d_out;

    cudaFuncSetAttribute(gemm_mma, cudaFuncAttributeMaxDynamicSharedMemorySize, GEMM_SMEM);

    __nv_bfloat16 *xh, *xl, *wh, *wl, *ph, *pl, *oh, *ol;
    cudaGetSymbolAddress((void**)&xh, g_xh);
    cudaGetSymbolAddress((void**)&xl, g_xl);
    cudaGetSymbolAddress((void**)&wh, g_wh);
    cudaGetSymbolAddress((void**)&wl, g_wl);
    cudaGetSymbolAddress((void**)&ph, g_ph);
    cudaGetSymbolAddress((void**)&pl, g_pl);
    cudaGetSymbolAddress((void**)&oh, g_oh);
    cudaGetSymbolAddress((void**)&ol, g_ol);

    splitb_kernel<<<(2048*49*384/4 + 255)/256, 256>>>(x, xh, xl, 2048*49*384/4);
    splitb_kernel<<<(1152*384/4 + 255)/256, 256>>>(qkv_w, wh, wl, 1152*384/4);
    splitb_kernel<<<(384*384/4 + 255)/256, 256>>>(proj_w, ph, pl, 384*384/4);

    cpb_kernel<<<169, 512>>>(table, cpb_w1, cpb_b1, cpb_w2);
    gather_kernel<<<(12 * 2401 + 255) / 256, 256>>>(idx);

    gemm_mma<<<dim3(784, 9), 256, GEMM_SMEM>>>(xh, xl, wh, wl, 0,
                                               q_bias, v_bias, nullptr, nullptr);
    attn_kernel<<<2048 * 12, 256>>>(mask, logit_scale);
    gemm_mma<<<dim3(784, 3), 256, GEMM_SMEM>>>(oh, ol, ph, pl, 1,
                                               nullptr, nullptr, proj_b, out);
}

// round 7
// speedup vs baseline: 2.3841x; 1.0084x over previous
#include <cuda_runtime.h>
#include <cuda_bf16.h>
#include <math.h>
#include <stdint.h>

// B=2048 windows, N=49, C=384, H=12, hd=32, nW=64
__device__ float g_q  [2048u*12*49*32];
__device__ float g_k  [2048u*12*49*32];
__device__ float g_v  [2048u*12*49*32];
__device__ __nv_bfloat16 g_oh[2048u*49*384];
__device__ __nv_bfloat16 g_ol[2048u*49*384];
__device__ __nv_bfloat16 g_xh[2048u*49*384];
__device__ __nv_bfloat16 g_xl[2048u*49*384];
__device__ __nv_bfloat16 g_wh[1152*384];
__device__ __nv_bfloat16 g_wl[1152*384];
__device__ __nv_bfloat16 g_ph[384*384];
__device__ __nv_bfloat16 g_pl[384*384];
__device__ float g_bt [169*12];
__device__ float g_rpb[12*49*49];

// ---------------------------------------------------------------------------
__device__ __forceinline__ uint32_t smem_u32(const void* p) {
    uint32_t a;
    asm("{ .reg .u64 t; cvta.to.shared.u64 t, %1; cvt.u32.u64 %0, t; }" : "=r"(a) : "l"(p));
    return a;
}
__device__ __forceinline__ void cp_async16(uint32_t dst, const void* src) {
    asm volatile("cp.async.cg.shared.global [%0], [%1], 16;" :: "r"(dst), "l"(src));
}
#define CP_COMMIT() asm volatile("cp.async.commit_group;" ::: "memory")
template<int N> __device__ __forceinline__ void cp_wait() {
    asm volatile("cp.async.wait_group %0;" :: "n"(N) : "memory");
}
__device__ __forceinline__ void ldsm4(uint32_t& r0, uint32_t& r1, uint32_t& r2, uint32_t& r3,
                                      uint32_t addr) {
    asm volatile("ldmatrix.sync.aligned.m8n8.x4.shared.b16 {%0,%1,%2,%3}, [%4];"
                 : "=r"(r0), "=r"(r1), "=r"(r2), "=r"(r3) : "r"(addr));
}
__device__ __forceinline__ void mma_bf16(float& c0, float& c1, float& c2, float& c3,
                                         uint32_t a0, uint32_t a1, uint32_t a2, uint32_t a3,
                                         uint32_t b0, uint32_t b1) {
    asm volatile("mma.sync.aligned.m16n8k16.row.col.f32.bf16.bf16.f32 "
                 "{%0,%1,%2,%3}, {%4,%5,%6,%7}, {%8,%9}, {%0,%1,%2,%3};"
                 : "+f"(c0), "+f"(c1), "+f"(c2), "+f"(c3)
                 : "r"(a0), "r"(a1), "r"(a2), "r"(a3), "r"(b0), "r"(b1));
}

// ---------------------------------------------------------------------------
__global__ void splitb_kernel(const float* __restrict__ in, __nv_bfloat16* __restrict__ hi,
                              __nv_bfloat16* __restrict__ lo, int n4) {
    int i = blockIdx.x * 256 + threadIdx.x;
    if (i >= n4) return;
    float4 v = ((const float4*)in)[i];
    float vv[4] = {v.x, v.y, v.z, v.w};
    __nv_bfloat16 h[4], l[4];
    #pragma unroll
    for (int j = 0; j < 4; j++) {
        h[j] = __float2bfloat16(vv[j]);
        l[j] = __float2bfloat16(vv[j] - __bfloat162float(h[j]));
    }
    ((__nv_bfloat162*)hi)[2*i]   = __nv_bfloat162{h[0], h[1]};
    ((__nv_bfloat162*)hi)[2*i+1] = __nv_bfloat162{h[2], h[3]};
    ((__nv_bfloat162*)lo)[2*i]   = __nv_bfloat162{l[0], l[1]};
    ((__nv_bfloat162*)lo)[2*i+1] = __nv_bfloat162{l[2], l[3]};
}

// ---------------------------------------------------------------------------
__global__ void cpb_kernel(const float* __restrict__ table, const float* __restrict__ w1,
                           const float* __restrict__ b1, const float* __restrict__ w2) {
    __shared__ float red[16];
    int t = blockIdx.x, j = threadIdx.x;
    float t0 = table[t * 2 + 0], t1 = table[t * 2 + 1];
    float h = fmaxf(fmaf(t0, w1[j * 2 + 0], fmaf(t1, w1[j * 2 + 1], b1[j])), 0.f);
    for (int hh = 0; hh < 12; hh++) {
        float v = h * w2[hh * 512 + j];
        #pragma unroll
        for (int o = 16; o > 0; o >>= 1) v += __shfl_down_sync(0xffffffffu, v, o);
        if ((j & 31) == 0) red[j >> 5] = v;
        __syncthreads();
        if (j == 0) {
            float s = 0.f;
            #pragma unroll
            for (int w = 0; w < 16; w++) s += red[w];
            g_bt[t * 12 + hh] = 16.f / (1.f + expf(-s));
        }
        __syncthreads();
    }
}
__global__ void gather_kernel(const int* __restrict__ idx) {
    int e = blockIdx.x * 256 + threadIdx.x;
    if (e >= 12 * 49 * 49) return;
    int h = e / 2401, ij = e - h * 2401;
    g_rpb[e] = g_bt[idx[ij] * 12 + h];
}

// ---------------------------------------------------------------------------
// 3xBF16 warp-MMA GEMM v2: 512 threads, 16 warps 4x4, warp tile 32x32,
// 3-stage cp.async pipeline. 128x128 block tile, k-chunk 32.
// ---------------------------------------------------------------------------
#define PITCHE 40
#define COMP_B (128 * PITCHE * 2)       // 10240 B per component tile
#define STAGE_B (4 * COMP_B)            // 40960
#define NSTAGE 3
#define GEMM_SMEM (NSTAGE * STAGE_B)    // 122880

__global__ void __launch_bounds__(512) gemm_mma(
    const __nv_bfloat16* __restrict__ Ahi, const __nv_bfloat16* __restrict__ Alo,
    const __nv_bfloat16* __restrict__ Bhi, const __nv_bfloat16* __restrict__ Blo, int mode,
    const float* __restrict__ bq, const float* __restrict__ bv,
    const float* __restrict__ bp, float* __restrict__ outp)
{
    extern __shared__ char sm[];
    uint32_t sbase = smem_u32(sm);
    int tid = threadIdx.x, wid = tid >> 5, lane = tid & 31;
    int g = lane >> 2, t = lane & 3;
    int grp = lane >> 3, rin = lane & 7;
    int m0 = blockIdx.x * 128, n0 = blockIdx.y * 128;
    int wm = (wid >> 2) * 32;
    int wn = (wid & 3) * 32;

    float c[2][4][4];
    #pragma unroll
    for (int mi = 0; mi < 2; mi++)
        #pragma unroll
        for (int nj = 0; nj < 4; nj++)
            #pragma unroll
            for (int r = 0; r < 4; r++) c[mi][nj][r] = 0.f;

    int aoff[2], boff[2];
    #pragma unroll
    for (int mi = 0; mi < 2; mi++)
        aoff[mi] = (wm + 16 * mi + (grp & 1) * 8 + rin) * PITCHE + (grp >> 1) * 8;
    #pragma unroll
    for (int j = 0; j < 2; j++)
        boff[j] = (wn + 16 * j + (grp >> 1) * 8 + rin) * PITCHE + (grp & 1) * 8;

    auto load_stage = [&](int it, int s) {
        int k0 = it * 32;
        uint32_t sb = sbase + s * STAGE_B;
        int r = tid >> 2, seg = tid & 3;
        uint32_t off = (uint32_t)(r * (PITCHE * 2) + seg * 16);
        size_t ga = (size_t)(m0 + r) * 384 + k0 + seg * 8;
        size_t gb = (size_t)(n0 + r) * 384 + k0 + seg * 8;
        cp_async16(sb + 0 * COMP_B + off, Ahi + ga);
        cp_async16(sb + 1 * COMP_B + off, Alo + ga);
        cp_async16(sb + 2 * COMP_B + off, Bhi + gb);
        cp_async16(sb + 3 * COMP_B + off, Blo + gb);
        CP_COMMIT();
    };

    load_stage(0, 0);
    load_stage(1, 1);
    load_stage(2, 2);

    for (int it = 0; it < 12; ++it) {
        int s = it % NSTAGE;
        if (it <= 9) cp_wait<2>(); else if (it == 10) cp_wait<1>(); else cp_wait<0>();
        __syncthreads();
        uint32_t sb = sbase + s * STAGE_B;
        #pragma unroll
        for (int kc = 0; kc < 32; kc += 16) {
            uint32_t ah[2][4], al[2][4], bh[2][4], bl[2][4];
            #pragma unroll
            for (int mi = 0; mi < 2; mi++) {
                uint32_t ao = sb + (uint32_t)((aoff[mi] + kc) * 2);
                ldsm4(ah[mi][0], ah[mi][1], ah[mi][2], ah[mi][3], ao + 0 * COMP_B);
                ldsm4(al[mi][0], al[mi][1], al[mi][2], al[mi][3], ao + 1 * COMP_B);
            }
            #pragma unroll
            for (int j = 0; j < 2; j++) {
                uint32_t bo = sb + (uint32_t)((boff[j] + kc) * 2);
                ldsm4(bh[j][0], bh[j][1], bh[j][2], bh[j][3], bo + 2 * COMP_B);
                ldsm4(bl[j][0], bl[j][1], bl[j][2], bl[j][3], bo + 3 * COMP_B);
            }
            #pragma unroll
            for (int mi = 0; mi < 2; mi++)
                #pragma unroll
                for (int nj = 0; nj < 4; nj++) {
                    int j = nj >> 1, hf = (nj & 1) * 2;
                    mma_bf16(c[mi][nj][0], c[mi][nj][1], c[mi][nj][2], c[mi][nj][3],
                             ah[mi][0], ah[mi][1], ah[mi][2], ah[mi][3],
                             bl[j][hf], bl[j][hf + 1]);
                    mma_bf16(c[mi][nj][0], c[mi][nj][1], c[mi][nj][2], c[mi][nj][3],
                             al[mi][0], al[mi][1], al[mi][2], al[mi][3],
                             bh[j][hf], bh[j][hf + 1]);
                    mma_bf16(c[mi][nj][0], c[mi][nj][1], c[mi][nj][2], c[mi][nj][3],
                             ah[mi][0], ah[mi][1], ah[mi][2], ah[mi][3],
                             bh[j][hf], bh[j][hf + 1]);
                }
        }
        __syncthreads();
        if (it + NSTAGE < 12) load_stage(it + NSTAGE, s);
    }

    #pragma unroll
    for (int mi = 0; mi < 2; mi++) {
        #pragma unroll
        for (int half = 0; half < 2; half++) {
            int row = m0 + wm + 16 * mi + g + 8 * half;
            int b = row / 49, nn = row - b * 49;
            #pragma unroll
            for (int nj = 0; nj < 4; nj++) {
                int col = n0 + wn + 8 * nj + 2 * t;
                float2 v;
                v.x = c[mi][nj][2 * half + 0];
                v.y = c[mi][nj][2 * half + 1];
                if (mode == 0) {
                    int which = col / 384;
                    int rem = col - which * 384;
                    int h = rem >> 5, d = rem & 31;
                    if (which == 0)      { v.x += bq[rem]; v.y += bq[rem + 1]; }
                    else if (which == 2) { v.x += bv[rem]; v.y += bv[rem + 1]; }
                    float* dst = ((which == 0) ? g_q : (which == 1) ? g_k : g_v)
                                 + (((size_t)b * 12 + h) * 49 + nn) * 32 + d;
                    *(float2*)dst = v;
                } else {
                    v.x += bp[col]; v.y += bp[col + 1];
                    *(float2*)(outp + (size_t)row * 384 + col) = v;
                }
            }
        }
    }
}

// ---------------------------------------------------------------------------
// Attention v2 (unchanged from round 6)
// ---------------------------------------------------------------------------
#define QP 36
#define SP 50

__global__ void __launch_bounds__(256) attn_kernel(const float* __restrict__ mask,
                                                   const float* __restrict__ logit_scale)
{
    __shared__ float sq[49 * QP];
    __shared__ float sk[49 * QP];
    __shared__ float sv[49 * QP];
    __shared__ float sS[49 * SP];
    __shared__ float sredA[245];
    __shared__ float sredB[245];
    int bh = blockIdx.x;
    int b = bh / 12, h = bh - b * 12;
    int tid = threadIdx.x;

    size_t base = (size_t)bh * 49 * 32;
    const float4* gq4 = (const float4*)(g_q + base);
    const float4* gk4 = (const float4*)(g_k + base);
    const float4* gv4 = (const float4*)(g_v + base);
    for (int u = tid; u < 392; u += 256) {
        int r = u >> 3, c4 = (u & 7) * 4;
        *(float4*)(sq + r * QP + c4) = gq4[u];
        *(float4*)(sk + r * QP + c4) = gk4[u];
        *(float4*)(sv + r * QP + c4) = gv4[u];
    }
    __syncthreads();

    if (tid < 98) {
        int r = (tid < 49) ? tid : tid - 49;
        float* s = (tid < 49) ? sq : sk;
        float ss = 0.f;
        #pragma unroll
        for (int d = 0; d < 32; d++) { float x = s[r * QP + d]; ss = fmaf(x, x, ss); }
        float inv = 1.f / fmaxf(sqrtf(ss), 1e-12f);
        if (tid < 49) inv *= expf(fminf(logit_scale[h], 4.60517018598809136804f));
        #pragma unroll
        for (int d = 0; d < 32; d++) s[r * QP + d] *= inv;
    }
    __syncthreads();

    if (tid < 125) {
        int ip = tid / 5, jg = tid - ip * 5;
        int i0 = ip * 2, i1 = i0 + 1;
        bool has1 = (i1 < 49);
        float4 qa[8], qb[8];
        #pragma unroll
        for (int u = 0; u < 8; u++) qa[u] = *(const float4*)(sq + i0 * QP + u * 4);
        if (has1) {
            #pragma unroll
            for (int u = 0; u < 8; u++) qb[u] = *(const float4*)(sq + i1 * QP + u * 4);
        }
        #pragma unroll
        for (int jj = 0; jj < 10; jj++) {
            int j = jg * 10 + jj;
            if (j >= 49) break;
            float a0 = 0.f, a1 = 0.f;
            #pragma unroll
            for (int u = 0; u < 8; u++) {
                float4 kv = *(const float4*)(sk + j * QP + u * 4);
                a0 = fmaf(qa[u].x, kv.x, a0); a0 = fmaf(qa[u].y, kv.y, a0);
                a0 = fmaf(qa[u].z, kv.z, a0); a0 = fmaf(qa[u].w, kv.w, a0);
                if (has1) {
                    a1 = fmaf(qb[u].x, kv.x, a1); a1 = fmaf(qb[u].y, kv.y, a1);
                    a1 = fmaf(qb[u].z, kv.z, a1); a1 = fmaf(qb[u].w, kv.w, a1);
                }
            }
            sS[i0 * SP + j] = a0;
            if (has1) sS[i1 * SP + j] = a1;
        }
    }
    __syncthreads();

    int si = tid / 5, sp = tid - si * 5;
    int j0 = sp * 10, j1 = min(j0 + 10, 49);
    if (tid < 245) {
        const float* rp = g_rpb + (h * 49 + si) * 49;
        const float* mp = mask + ((size_t)(b & 63) * 49 + si) * 49;
        float lmax = -1e30f;
        for (int j = j0; j < j1; j++) {
            float s = sS[si * SP + j] + rp[j] + mp[j];
            sS[si * SP + j] = s;
            lmax = fmaxf(lmax, s);
        }
        sredA[tid] = lmax;
    }
    __syncthreads();
    if (tid < 245) {
        float mx = sredA[si * 5];
        #pragma unroll
        for (int p = 1; p < 5; p++) mx = fmaxf(mx, sredA[si * 5 + p]);
        float lsum = 0.f;
        for (int j = j0; j < j1; j++) {
            float e = expf(sS[si * SP + j] - mx);
            sS[si * SP + j] = e;
            lsum += e;
        }
        sredB[tid] = lsum;
    }
    __syncthreads();
    if (tid < 245) {
        float sum = sredB[si * 5];
        #pragma unroll
        for (int p = 1; p < 5; p++) sum += sredB[si * 5 + p];
        float inv = 1.f / sum;
        for (int j = j0; j < j1; j++) sS[si * SP + j] *= inv;
    }
    __syncthreads();

    if (tid < 104) {
        int ipart = tid >> 3, dq = tid & 7;
        int r0 = ipart * 4;
        float4 acc[4] = {{0,0,0,0},{0,0,0,0},{0,0,0,0},{0,0,0,0}};
        for (int j = 0; j < 49; j++) {
            float4 v = *(const float4*)(sv + j * QP + dq * 4);
            #pragma unroll
            for (int rr = 0; rr < 4; rr++) {
                int r = r0 + rr;
                float s = (r < 49) ? sS[r * SP + j] : 0.f;
                acc[rr].x = fmaf(s, v.x, acc[rr].x);
                acc[rr].y = fmaf(s, v.y, acc[rr].y);
                acc[rr].z = fmaf(s, v.z, acc[rr].z);
                acc[rr].w = fmaf(s, v.w, acc[rr].w);
            }
        }
        #pragma unroll
        for (int rr = 0; rr < 4; rr++) {
            int r = r0 + rr;
            if (r < 49) {
                size_t oidx = ((size_t)b * 49 + r) * 384 + h * 32 + dq * 4;
                float av[4] = {acc[rr].x, acc[rr].y, acc[rr].z, acc[rr].w};
                __nv_bfloat16 hh[4], ll[4];
                #pragma unroll
                for (int e = 0; e < 4; e++) {
                    hh[e] = __float2bfloat16(av[e]);
                    ll[e] = __float2bfloat16(av[e] - __bfloat162float(hh[e]));
                }
                *(__nv_bfloat162*)(g_oh + oidx)     = __nv_bfloat162{hh[0], hh[1]};
                *(__nv_bfloat162*)(g_oh + oidx + 2) = __nv_bfloat162{hh[2], hh[3]};
                *(__nv_bfloat162*)(g_ol + oidx)     = __nv_bfloat162{ll[0], ll[1]};
                *(__nv_bfloat162*)(g_ol + oidx + 2) = __nv_bfloat162{ll[2], ll[3]};
            }
        }
    }
}

// ---------------------------------------------------------------------------
extern "C" void kernel_launch(void* const* d_in, const int* in_sizes, int n_in,
                              void* d_out, int out_size) {
    const float* x           = (const float*)d_in[0];
    const float* mask        = (const float*)d_in[1];
    const float* qkv_w       = (const float*)d_in[2];
    const float* q_bias      = (const float*)d_in[3];
    const float* v_bias      = (const float*)d_in[4];
    const float* logit_scale = (const float*)d_in[5];
    const float* cpb_w1      = (const float*)d_in[6];
    const float* cpb_b1      = (const float*)d_in[7];
    const float* cpb_w2      = (const float*)d_in[8];
    const float* proj_w      = (const float*)d_in[9];
    const float* proj_b      = (const float*)d_in[10];
    const float* table       = (const float*)d_in[11];
    const int*   idx         = (const int*)d_in[12];
    float* out = (float*)d_out;

    cudaFuncSetAttribute(gemm_mma, cudaFuncAttributeMaxDynamicSharedMemorySize, GEMM_SMEM);

    __nv_bfloat16 *xh, *xl, *wh, *wl, *ph, *pl, *oh, *ol;
    cudaGetSymbolAddress((void**)&xh, g_xh);
    cudaGetSymbolAddress((void**)&xl, g_xl);
    cudaGetSymbolAddress((void**)&wh, g_wh);
    cudaGetSymbolAddress((void**)&wl, g_wl);
    cudaGetSymbolAddress((void**)&ph, g_ph);
    cudaGetSymbolAddress((void**)&pl, g_pl);
    cudaGetSymbolAddress((void**)&oh, g_oh);
    cudaGetSymbolAddress((void**)&ol, g_ol);

    splitb_kernel<<<(2048*49*384/4 + 255)/256, 256>>>(x, xh, xl, 2048*49*384/4);
    splitb_kernel<<<(1152*384/4 + 255)/256, 256>>>(qkv_w, wh, wl, 1152*384/4);
    splitb_kernel<<<(384*384/4 + 255)/256, 256>>>(proj_w, ph, pl, 384*384/4);

    cpb_kernel<<<169, 512>>>(table, cpb_w1, cpb_b1, cpb_w2);
    gather_kernel<<<(12 * 2401 + 255) / 256, 256>>>(idx);

    gemm_mma<<<dim3(784, 9), 512, GEMM_SMEM>>>(xh, xl, wh, wl, 0,
                                               q_bias, v_bias, nullptr, nullptr);
    attn_kernel<<<2048 * 12, 256>>>(mask, logit_scale);
    gemm_mma<<<dim3(784, 3), 512, GEMM_SMEM>>>(oh, ol, ph, pl, 1,
                                               nullptr, nullptr, proj_b, out);
}

// round 8
// speedup vs baseline: 2.5112x; 1.0533x over previous
#include <cuda_runtime.h>
#include <cuda_fp16.h>
#include <math.h>
#include <stdint.h>

// B=2048 windows, N=49, C=384, H=12, hd=32, nW=64
__device__ float g_q  [2048u*12*49*32];
__device__ float g_k  [2048u*12*49*32];
__device__ float g_v  [2048u*12*49*32];
__device__ __half g_oh[2048u*49*384];   // attn out hi (fp16)
__device__ __half g_ol[2048u*49*384];   // attn out lo (fp16, x2048)
__device__ __half g_xh[2048u*49*384];
__device__ __half g_xl[2048u*49*384];   // x residual, x2048
__device__ __half g_wh[1152*384];
__device__ __half g_wl[1152*384];       // w residual, x2048
__device__ __half g_ph[384*384];
__device__ __half g_pl[384*384];        // proj residual, x2048
__device__ float g_bt [169*12];
__device__ float g_rpb[12*49*49];

#define LO_SCALE 2048.f
#define LO_INV   (1.f / 2048.f)

// ---------------------------------------------------------------------------
__device__ __forceinline__ uint32_t smem_u32(const void* p) {
    uint32_t a;
    asm("{ .reg .u64 t; cvta.to.shared.u64 t, %1; cvt.u32.u64 %0, t; }" : "=r"(a) : "l"(p));
    return a;
}
__device__ __forceinline__ void cp_async16(uint32_t dst, const void* src) {
    asm volatile("cp.async.cg.shared.global [%0], [%1], 16;" :: "r"(dst), "l"(src));
}
#define CP_COMMIT() asm volatile("cp.async.commit_group;" ::: "memory")
template<int N> __device__ __forceinline__ void cp_wait() {
    asm volatile("cp.async.wait_group %0;" :: "n"(N) : "memory");
}
__device__ __forceinline__ void ldsm4(uint32_t& r0, uint32_t& r1, uint32_t& r2, uint32_t& r3,
                                      uint32_t addr) {
    asm volatile("ldmatrix.sync.aligned.m8n8.x4.shared.b16 {%0,%1,%2,%3}, [%4];"
                 : "=r"(r0), "=r"(r1), "=r"(r2), "=r"(r3) : "r"(addr));
}
__device__ __forceinline__ void mma_f16(float& c0, float& c1, float& c2, float& c3,
                                        uint32_t a0, uint32_t a1, uint32_t a2, uint32_t a3,
                                        uint32_t b0, uint32_t b1) {
    asm volatile("mma.sync.aligned.m16n8k16.row.col.f32.f16.f16.f32 "
                 "{%0,%1,%2,%3}, {%4,%5,%6,%7}, {%8,%9}, {%0,%1,%2,%3};"
                 : "+f"(c0), "+f"(c1), "+f"(c2), "+f"(c3)
                 : "r"(a0), "r"(a1), "r"(a2), "r"(a3), "r"(b0), "r"(b1));
}

// ---------------------------------------------------------------------------
// fp16 hi/lo split: hi = f16(x), lo = f16((x - hi) * 2048)
// ---------------------------------------------------------------------------
__global__ void splith_kernel(const float* __restrict__ in, __half* __restrict__ hi,
                              __half* __restrict__ lo, int n4) {
    int i = blockIdx.x * 256 + threadIdx.x;
    if (i >= n4) return;
    float4 v = ((const float4*)in)[i];
    float vv[4] = {v.x, v.y, v.z, v.w};
    __half h[4], l[4];
    #pragma unroll
    for (int j = 0; j < 4; j++) {
        h[j] = __float2half_rn(vv[j]);
        l[j] = __float2half_rn((vv[j] - __half2float(h[j])) * LO_SCALE);
    }
    ((__half2*)hi)[2*i]   = __half2{h[0], h[1]};
    ((__half2*)hi)[2*i+1] = __half2{h[2], h[3]};
    ((__half2*)lo)[2*i]   = __half2{l[0], l[1]};
    ((__half2*)lo)[2*i+1] = __half2{l[2], l[3]};
}

// ---------------------------------------------------------------------------
// CPB MLP + gather
// ---------------------------------------------------------------------------
__global__ void cpb_kernel(const float* __restrict__ table, const float* __restrict__ w1,
                           const float* __restrict__ b1, const float* __restrict__ w2) {
    __shared__ float red[16];
    int t = blockIdx.x, j = threadIdx.x;
    float t0 = table[t * 2 + 0], t1 = table[t * 2 + 1];
    float h = fmaxf(fmaf(t0, w1[j * 2 + 0], fmaf(t1, w1[j * 2 + 1], b1[j])), 0.f);
    for (int hh = 0; hh < 12; hh++) {
        float v = h * w2[hh * 512 + j];
        #pragma unroll
        for (int o = 16; o > 0; o >>= 1) v += __shfl_down_sync(0xffffffffu, v, o);
        if ((j & 31) == 0) red[j >> 5] = v;
        __syncthreads();
        if (j == 0) {
            float s = 0.f;
            #pragma unroll
            for (int w = 0; w < 16; w++) s += red[w];
            g_bt[t * 12 + hh] = 16.f / (1.f + expf(-s));
        }
        __syncthreads();
    }
}
__global__ void gather_kernel(const int* __restrict__ idx) {
    int e = blockIdx.x * 256 + threadIdx.x;
    if (e >= 12 * 49 * 49) return;
    int h = e / 2401, ij = e - h * 2401;
    g_rpb[e] = g_bt[idx[ij] * 12 + h];
}

// ---------------------------------------------------------------------------
// fp16-limb warp-MMA GEMM. TERMS=3: hi*hi + (lo*hi + hi*lo)/2048.
// TERMS=2: hi*hi + (lo_A*hi_B)/2048 (drops hi*lo, err ~2^-12 — only for
// v-columns and proj where error passes linearly).
// 512 thr, 16 warps 4x4, warp tile 32x32, 3-stage cp.async, 128x128 tile.
// ---------------------------------------------------------------------------
#define PITCHE 40
#define COMP_B (128 * PITCHE * 2)
#define STAGE_B (4 * COMP_B)
#define NSTAGE 3
#define GEMM_SMEM (NSTAGE * STAGE_B)

template<int TERMS>
__global__ void __launch_bounds__(512) gemm_mma(
    const __half* __restrict__ Ahi, const __half* __restrict__ Alo,
    const __half* __restrict__ Bhi, const __half* __restrict__ Blo,
    int mode, int n_base,
    const float* __restrict__ bq, const float* __restrict__ bv,
    const float* __restrict__ bp, float* __restrict__ outp)
{
    extern __shared__ char sm[];
    uint32_t sbase = smem_u32(sm);
    int tid = threadIdx.x, wid = tid >> 5, lane = tid & 31;
    int g = lane >> 2, t = lane & 3;
    int grp = lane >> 3, rin = lane & 7;
    int m0 = blockIdx.x * 128, n0 = n_base + blockIdx.y * 128;
    int wm = (wid >> 2) * 32;
    int wn = (wid & 3) * 32;

    float cm[2][4][4], cx[2][4][4];
    #pragma unroll
    for (int mi = 0; mi < 2; mi++)
        #pragma unroll
        for (int nj = 0; nj < 4; nj++)
            #pragma unroll
            for (int r = 0; r < 4; r++) { cm[mi][nj][r] = 0.f; cx[mi][nj][r] = 0.f; }

    int aoff[2], boff[2];
    #pragma unroll
    for (int mi = 0; mi < 2; mi++)
        aoff[mi] = (wm + 16 * mi + (grp & 1) * 8 + rin) * PITCHE + (grp >> 1) * 8;
    #pragma unroll
    for (int j = 0; j < 2; j++)
        boff[j] = (wn + 16 * j + (grp >> 1) * 8 + rin) * PITCHE + (grp & 1) * 8;

    auto load_stage = [&](int it, int s) {
        int k0 = it * 32;
        uint32_t sb = sbase + s * STAGE_B;
        int r = tid >> 2, seg = tid & 3;
        uint32_t off = (uint32_t)(r * (PITCHE * 2) + seg * 16);
        size_t ga = (size_t)(m0 + r) * 384 + k0 + seg * 8;
        size_t gb = (size_t)(n0 + r) * 384 + k0 + seg * 8;
        cp_async16(sb + 0 * COMP_B + off, Ahi + ga);
        cp_async16(sb + 1 * COMP_B + off, Alo + ga);
        cp_async16(sb + 2 * COMP_B + off, Bhi + gb);
        if (TERMS == 3) cp_async16(sb + 3 * COMP_B + off, Blo + gb);
        CP_COMMIT();
    };

    load_stage(0, 0);
    load_stage(1, 1);
    load_stage(2, 2);

    for (int it = 0; it < 12; ++it) {
        int s = it % NSTAGE;
        if (it <= 9) cp_wait<2>(); else if (it == 10) cp_wait<1>(); else cp_wait<0>();
        __syncthreads();
        uint32_t sb = sbase + s * STAGE_B;
        #pragma unroll
        for (int kc = 0; kc < 32; kc += 16) {
            uint32_t ah[2][4], al[2][4], bh[2][4], bl[2][4];
            #pragma unroll
            for (int mi = 0; mi < 2; mi++) {
                uint32_t ao = sb + (uint32_t)((aoff[mi] + kc) * 2);
                ldsm4(ah[mi][0], ah[mi][1], ah[mi][2], ah[mi][3], ao + 0 * COMP_B);
                ldsm4(al[mi][0], al[mi][1], al[mi][2], al[mi][3], ao + 1 * COMP_B);
            }
            #pragma unroll
            for (int j = 0; j < 2; j++) {
                uint32_t bo = sb + (uint32_t)((boff[j] + kc) * 2);
                ldsm4(bh[j][0], bh[j][1], bh[j][2], bh[j][3], bo + 2 * COMP_B);
                if (TERMS == 3)
                    ldsm4(bl[j][0], bl[j][1], bl[j][2], bl[j][3], bo + 3 * COMP_B);
            }
            #pragma unroll
            for (int mi = 0; mi < 2; mi++)
                #pragma unroll
                for (int nj = 0; nj < 4; nj++) {
                    int j = nj >> 1, hf = (nj & 1) * 2;
                    mma_f16(cm[mi][nj][0], cm[mi][nj][1], cm[mi][nj][2], cm[mi][nj][3],
                            ah[mi][0], ah[mi][1], ah[mi][2], ah[mi][3],
                            bh[j][hf], bh[j][hf + 1]);
                    mma_f16(cx[mi][nj][0], cx[mi][nj][1], cx[mi][nj][2], cx[mi][nj][3],
                            al[mi][0], al[mi][1], al[mi][2], al[mi][3],
                            bh[j][hf], bh[j][hf + 1]);
                    if (TERMS == 3)
                        mma_f16(cx[mi][nj][0], cx[mi][nj][1], cx[mi][nj][2], cx[mi][nj][3],
                                ah[mi][0], ah[mi][1], ah[mi][2], ah[mi][3],
                                bl[j][hf], bl[j][hf + 1]);
                }
        }
        __syncthreads();
        if (it + NSTAGE < 12) load_stage(it + NSTAGE, s);
    }

    #pragma unroll
    for (int mi = 0; mi < 2; mi++) {
        #pragma unroll
        for (int half = 0; half < 2; half++) {
            int row = m0 + wm + 16 * mi + g + 8 * half;
            int b = row / 49, nn = row - b * 49;
            #pragma unroll
            for (int nj = 0; nj < 4; nj++) {
                int col = n0 + wn + 8 * nj + 2 * t;
                float2 v;
                v.x = fmaf(cx[mi][nj][2 * half + 0], LO_INV, cm[mi][nj][2 * half + 0]);
                v.y = fmaf(cx[mi][nj][2 * half + 1], LO_INV, cm[mi][nj][2 * half + 1]);
                if (mode == 0) {
                    int which = col / 384;
                    int rem = col - which * 384;
                    int h = rem >> 5, d = rem & 31;
                    if (which == 0)      { v.x += bq[rem]; v.y += bq[rem + 1]; }
                    else if (which == 2) { v.x += bv[rem]; v.y += bv[rem + 1]; }
                    float* dst = ((which == 0) ? g_q : (which == 1) ? g_k : g_v)
                                 + (((size_t)b * 12 + h) * 49 + nn) * 32 + d;
                    *(float2*)dst = v;
                } else {
                    v.x += bp[col]; v.y += bp[col + 1];
                    *(float2*)(outp + (size_t)row * 384 + col) = v;
                }
            }
        }
    }
}

// ---------------------------------------------------------------------------
// Attention (round-6 structure); writes fp16 hi + scaled lo for proj input.
// ---------------------------------------------------------------------------
#define QP 36
#define SP 50

__global__ void __launch_bounds__(256) attn_kernel(const float* __restrict__ mask,
                                                   const float* __restrict__ logit_scale)
{
    __shared__ float sq[49 * QP];
    __shared__ float sk[49 * QP];
    __shared__ float sv[49 * QP];
    __shared__ float sS[49 * SP];
    __shared__ float sredA[245];
    __shared__ float sredB[245];
    int bh = blockIdx.x;
    int b = bh / 12, h = bh - b * 12;
    int tid = threadIdx.x;

    size_t base = (size_t)bh * 49 * 32;
    const float4* gq4 = (const float4*)(g_q + base);
    const float4* gk4 = (const float4*)(g_k + base);
    const float4* gv4 = (const float4*)(g_v + base);
    for (int u = tid; u < 392; u += 256) {
        int r = u >> 3, c4 = (u & 7) * 4;
        *(float4*)(sq + r * QP + c4) = gq4[u];
        *(float4*)(sk + r * QP + c4) = gk4[u];
        *(float4*)(sv + r * QP + c4) = gv4[u];
    }
    __syncthreads();

    if (tid < 98) {
        int r = (tid < 49) ? tid : tid - 49;
        float* s = (tid < 49) ? sq : sk;
        float ss = 0.f;
        #pragma unroll
        for (int d = 0; d < 32; d++) { float x = s[r * QP + d]; ss = fmaf(x, x, ss); }
        float inv = 1.f / fmaxf(sqrtf(ss), 1e-12f);
        if (tid < 49) inv *= expf(fminf(logit_scale[h], 4.60517018598809136804f));
        #pragma unroll
        for (int d = 0; d < 32; d++) s[r * QP + d] *= inv;
    }
    __syncthreads();

    if (tid < 125) {
        int ip = tid / 5, jg = tid - ip * 5;
        int i0 = ip * 2, i1 = i0 + 1;
        bool has1 = (i1 < 49);
        float4 qa[8], qb[8];
        #pragma unroll
        for (int u = 0; u < 8; u++) qa[u] = *(const float4*)(sq + i0 * QP + u * 4);
        if (has1) {
            #pragma unroll
            for (int u = 0; u < 8; u++) qb[u] = *(const float4*)(sq + i1 * QP + u * 4);
        }
        #pragma unroll
        for (int jj = 0; jj < 10; jj++) {
            int j = jg * 10 + jj;
            if (j >= 49) break;
            float a0 = 0.f, a1 = 0.f;
            #pragma unroll
            for (int u = 0; u < 8; u++) {
                float4 kv = *(const float4*)(sk + j * QP + u * 4);
                a0 = fmaf(qa[u].x, kv.x, a0); a0 = fmaf(qa[u].y, kv.y, a0);
                a0 = fmaf(qa[u].z, kv.z, a0); a0 = fmaf(qa[u].w, kv.w, a0);
                if (has1) {
                    a1 = fmaf(qb[u].x, kv.x, a1); a1 = fmaf(qb[u].y, kv.y, a1);
                    a1 = fmaf(qb[u].z, kv.z, a1); a1 = fmaf(qb[u].w, kv.w, a1);
                }
            }
            sS[i0 * SP + j] = a0;
            if (has1) sS[i1 * SP + j] = a1;
        }
    }
    __syncthreads();

    int si = tid / 5, sp = tid - si * 5;
    int j0 = sp * 10, j1 = min(j0 + 10, 49);
    if (tid < 245) {
        const float* rp = g_rpb + (h * 49 + si) * 49;
        const float* mp = mask + ((size_t)(b & 63) * 49 + si) * 49;
        float lmax = -1e30f;
        for (int j = j0; j < j1; j++) {
            float s = sS[si * SP + j] + rp[j] + mp[j];
            sS[si * SP + j] = s;
            lmax = fmaxf(lmax, s);
        }
        sredA[tid] = lmax;
    }
    __syncthreads();
    if (tid < 245) {
        float mx = sredA[si * 5];
        #pragma unroll
        for (int p = 1; p < 5; p++) mx = fmaxf(mx, sredA[si * 5 + p]);
        float lsum = 0.f;
        for (int j = j0; j < j1; j++) {
            float e = expf(sS[si * SP + j] - mx);
            sS[si * SP + j] = e;
            lsum += e;
        }
        sredB[tid] = lsum;
    }
    __syncthreads();
    if (tid < 245) {
        float sum = sredB[si * 5];
        #pragma unroll
        for (int p = 1; p < 5; p++) sum += sredB[si * 5 + p];
        float inv = 1.f / sum;
        for (int j = j0; j < j1; j++) sS[si * SP + j] *= inv;
    }
    __syncthreads();

    if (tid < 104) {
        int ipart = tid >> 3, dq = tid & 7;
        int r0 = ipart * 4;
        float4 acc[4] = {{0,0,0,0},{0,0,0,0},{0,0,0,0},{0,0,0,0}};
        for (int j = 0; j < 49; j++) {
            float4 v = *(const float4*)(sv + j * QP + dq * 4);
            #pragma unroll
            for (int rr = 0; rr < 4; rr++) {
                int r = r0 + rr;
                float s = (r < 49) ? sS[r * SP + j] : 0.f;
                acc[rr].x = fmaf(s, v.x, acc[rr].x);
                acc[rr].y = fmaf(s, v.y, acc[rr].y);
                acc[rr].z = fmaf(s, v.z, acc[rr].z);
                acc[rr].w = fmaf(s, v.w, acc[rr].w);
            }
        }
        #pragma unroll
        for (int rr = 0; rr < 4; rr++) {
            int r = r0 + rr;
            if (r < 49) {
                size_t oidx = ((size_t)b * 49 + r) * 384 + h * 32 + dq * 4;
                float av[4] = {acc[rr].x, acc[rr].y, acc[rr].z, acc[rr].w};
                __half hh[4], ll[4];
                #pragma unroll
                for (int e = 0; e < 4; e++) {
                    hh[e] = __float2half_rn(av[e]);
                    ll[e] = __float2half_rn((av[e] - __half2float(hh[e])) * LO_SCALE);
                }
                *(__half2*)(g_oh + oidx)     = __half2{hh[0], hh[1]};
                *(__half2*)(g_oh + oidx + 2) = __half2{hh[2], hh[3]};
                *(__half2*)(g_ol + oidx)     = __half2{ll[0], ll[1]};
                *(__half2*)(g_ol + oidx + 2) = __half2{ll[2], ll[3]};
            }
        }
    }
}

// ---------------------------------------------------------------------------
extern "C" void kernel_launch(void* const* d_in, const int* in_sizes, int n_in,
                              void* d_out, int out_size) {
    const float* x           = (const float*)d_in[0];
    const float* mask        = (const float*)d_in[1];
    const float* qkv_w       = (const float*)d_in[2];
    const float* q_bias      = (const float*)d_in[3];
    const float* v_bias      = (const float*)d_in[4];
    const float* logit_scale = (const float*)d_in[5];
    const float* cpb_w1      = (const float*)d_in[6];
    const float* cpb_b1      = (const float*)d_in[7];
    const float* cpb_w2      = (const float*)d_in[8];
    const float* proj_w      = (const float*)d_in[9];
    const float* proj_b      = (const float*)d_in[10];
    const float* table       = (const float*)d_in[11];
    const int*   idx         = (const int*)d_in[12];
    float* out = (float*)d_out;

    cudaFuncSetAttribute(gemm_mma<3>, cudaFuncAttributeMaxDynamicSharedMemorySize, GEMM_SMEM);
    cudaFuncSetAttribute(gemm_mma<2>, cudaFuncAttributeMaxDynamicSharedMemorySize, GEMM_SMEM);

    __half *xh, *xl, *wh, *wl, *ph, *pl, *oh, *ol;
    cudaGetSymbolAddress((void**)&xh, g_xh);
    cudaGetSymbolAddress((void**)&xl, g_xl);
    cudaGetSymbolAddress((void**)&wh, g_wh);
    cudaGetSymbolAddress((void**)&wl, g_wl);
    cudaGetSymbolAddress((void**)&ph, g_ph);
    cudaGetSymbolAddress((void**)&pl, g_pl);
    cudaGetSymbolAddress((void**)&oh, g_oh);
    cudaGetSymbolAddress((void**)&ol, g_ol);

    splith_kernel<<<(2048*49*384/4 + 255)/256, 256>>>(x, xh, xl, 2048*49*384/4);
    splith_kernel<<<(1152*384/4 + 255)/256, 256>>>(qkv_w, wh, wl, 1152*384/4);
    splith_kernel<<<(384*384/4 + 255)/256, 256>>>(proj_w, ph, pl, 384*384/4);

    cpb_kernel<<<169, 512>>>(table, cpb_w1, cpb_b1, cpb_w2);
    gather_kernel<<<(12 * 2401 + 255) / 256, 256>>>(idx);

    // QKV: q,k columns (n 0..767) 3-term; v columns (n 768..1151) 2-term
    gemm_mma<3><<<dim3(784, 6), 512, GEMM_SMEM>>>(xh, xl, wh, wl, 0, 0,
                                                  q_bias, v_bias, nullptr, nullptr);
    gemm_mma<2><<<dim3(784, 3), 512, GEMM_SMEM>>>(xh, xl, wh, wl, 0, 768,
                                                  q_bias, v_bias, nullptr, nullptr);
    attn_kernel<<<2048 * 12, 256>>>(mask, logit_scale);
    gemm_mma<2><<<dim3(784, 3), 512, GEMM_SMEM>>>(oh, ol, ph, pl, 1, 0,
                                                  nullptr, nullptr, proj_b, out);
}